// round 4
// baseline (speedup 1.0000x reference)
#include <cuda_runtime.h>

#define NT    512
#define ROWS  16
#define NBLK  128          // 2048/16
#define TSEQ  256
#define FIN   64

typedef unsigned long long u64;

// ---- smem layout (float offsets) ----
#define WP0_N   (128*64*4)
#define WP1_N   (96*32*4)
#define WP2_N   (48*16*4)
#define WP0_OFF 0
#define WP1_OFF 32768
#define WP2_OFF 45056
#define BP0_OFF 48128
#define BP1_OFF 48384
#define BP2_OFF 48512
#define WDS_OFF 48576
#define BDS_OFF 48592
#define IN0_OFF 48608            // 128B aligned
#define IN0_STR 36               // floats per k-row (16 rows row-dup = 32 + pad 4)
#define IN0_N   (128*IN0_STR)    // 4608
#define IN1_OFF (IN0_OFF + IN0_N)   // 53216
#define IN1_N   (96*32)             // 3072
#define IN2_OFF (IN1_OFF + IN1_N)   // 56288
#define IN2_N   (48*32)             // 1536
#define SMEM_FLOATS (IN2_OFF + IN2_N)  // 57824
#define SMEM_BYTES  (SMEM_FLOATS * 4)  // 231296

__device__ __forceinline__ u64 ffma2(u64 a, u64 b, u64 c) {
    u64 d; asm("fma.rn.f32x2 %0, %1, %2, %3;" : "=l"(d) : "l"(a), "l"(b), "l"(c));
    return d;
}
__device__ __forceinline__ u64 dup2(float x) {
    u64 d; asm("mov.b64 %0, {%1, %1};" : "=l"(d) : "f"(x));
    return d;
}
__device__ __forceinline__ float2 unpk(u64 v) {
    float2 r; asm("mov.b64 {%0, %1}, %2;" : "=f"(r.x), "=f"(r.y) : "l"(v));
    return r;
}
__device__ __forceinline__ float tanhap(float x) {
    float y; asm("tanh.approx.f32 %0, %1;" : "=f"(y) : "f"(x));
    return y;
}
__device__ __forceinline__ float sigap(float x) {
    return fmaf(0.5f, tanhap(0.5f * x), 0.5f);
}

__global__ void __launch_bounds__(NT, 1) lstm3_fused_kernel(
    const float* __restrict__ x,
    const float* __restrict__ W0, const float* __restrict__ U0, const float* __restrict__ b0,
    const float* __restrict__ W1, const float* __restrict__ U1, const float* __restrict__ b1,
    const float* __restrict__ W2, const float* __restrict__ U2, const float* __restrict__ b2,
    const float* __restrict__ Wd, const float* __restrict__ bd,
    float* __restrict__ out)
{
    extern __shared__ float sm[];
    const int tid  = threadIdx.x;
    const int row0 = blockIdx.x * ROWS;

    float* wp0 = sm + WP0_OFF;
    float* wp1 = sm + WP1_OFF;
    float* wp2 = sm + WP2_OFF;
    float* bp0 = sm + BP0_OFF;
    float* bp1 = sm + BP1_OFF;
    float* bp2 = sm + BP2_OFF;
    float* wds = sm + WDS_OFF;
    float* bds = sm + BDS_OFF;
    float* in0 = sm + IN0_OFF;   // [k=128][36] row-dup; k<64 x_t, k>=64 h0
    float* in1 = sm + IN1_OFF;   // [k=96][32]  row-dup; k<64 h0, k>=64 h1
    float* in2 = sm + IN2_OFF;   // [k=48][32]  row-dup; k<32 h1, k>=32 h2

    // ---- load + rearrange weights: [k][u][g] (gate order i,f,g,o) ----
    for (int idx = tid; idx < WP0_N; idx += NT) {
        int g = idx & 3, u = (idx >> 2) & 63, k = idx >> 8;
        wp0[idx] = (k < 64) ? W0[k*256 + g*64 + u] : U0[(k-64)*256 + g*64 + u];
    }
    for (int idx = tid; idx < WP1_N; idx += NT) {
        int g = idx & 3, u = (idx >> 2) & 31, k = idx >> 7;
        wp1[idx] = (k < 64) ? W1[k*128 + g*32 + u] : U1[(k-64)*128 + g*32 + u];
    }
    for (int idx = tid; idx < WP2_N; idx += NT) {
        int g = idx & 3, u = (idx >> 2) & 15, k = idx >> 6;
        wp2[idx] = (k < 32) ? W2[k*64 + g*16 + u] : U2[(k-32)*64 + g*16 + u];
    }
    if (tid < 256) bp0[tid] = b0[(tid & 3)*64 + (tid >> 2)];
    if (tid < 128) bp1[tid] = b1[(tid & 3)*32 + (tid >> 2)];
    if (tid < 64)  bp2[tid] = b2[(tid & 3)*16 + (tid >> 2)];
    if (tid < 16)  wds[tid] = Wd[tid];
    if (tid == 0)  bds[0]   = bd[0];
    for (int idx = tid; idx < IN0_N; idx += NT) in0[idx] = 0.0f;
    for (int idx = tid; idx < IN1_N; idx += NT) in1[idx] = 0.0f;
    for (int idx = tid; idx < IN2_N; idx += NT) in2[idx] = 0.0f;
    __syncthreads();

    // ---- thread mappings (warp-local unit tiling) ----
    const int wrp = tid >> 5, lan = tid & 31;
    const int u0 = (wrp << 2) + (lan & 3), rg0 = lan >> 2;  // L0: 64 units x 8 rowgroups(2 rows)
    const int u1 = (wrp << 1) + (lan & 1), r1  = lan >> 1;  // L1: 32 units x 16 rows
    const int u2 = ((wrp & 7) << 1) + (lan & 1), r2 = lan >> 1;  // L2 (warps 0-7): 16 units x 16 rows
    const bool l2act = (wrp < 8);

    const ulonglong2 bias0 = reinterpret_cast<const ulonglong2*>(bp0)[u0]; // {bi,bf},{bg,bo}
    const ulonglong2 bias1 = reinterpret_cast<const ulonglong2*>(bp1)[u1];
    const ulonglong2 bias2 = reinterpret_cast<const ulonglong2*>(bp2)[u2];

    const ulonglong2* w0v = reinterpret_cast<const ulonglong2*>(wp0) + u0; // stride 64/k
    const ulonglong2* w1v = reinterpret_cast<const ulonglong2*>(wp1) + u1; // stride 32/k
    const ulonglong2* w2v = reinterpret_cast<const ulonglong2*>(wp2) + u2; // stride 16/k
    const float* h0b = in0 + 4*rg0;
    const float* h1b = in1 + 2*r1;
    const float* h2b = in2 + 2*r2;

    float c0[2] = {0.f, 0.f};
    float c1v   = 0.f;
    float c2v   = 0.f;

    // x staging: thread stages rows 2*ra, 2*ra+1 of feature f0
    const int f0 = tid & 63;
    const int ra = tid >> 6;              // 0..7
    const size_t xbase = (size_t)(row0 + 2*ra) * (TSEQ * FIN) + f0;
    float* xsts = in0 + f0*IN0_STR + 4*ra;
    float xr0 = x[xbase];
    float xr1 = x[xbase + (TSEQ*FIN)];
    *reinterpret_cast<float4*>(xsts) = make_float4(xr0, xr0, xr1, xr1);
    __syncthreads();

    for (int t = 0; t < TSEQ; ++t) {
        // prefetch x_{t+1}
        if (t + 1 < TSEQ) {
            xr0 = x[xbase + (size_t)(t+1)*FIN];
            xr1 = x[xbase + (size_t)(t+1)*FIN + (TSEQ*FIN)];
        }

        // ================= Layer 0: K=128, 2 rows x {if,go} =================
        u64 a00 = bias0.x, a01 = bias0.y, a10 = bias0.x, a11 = bias0.y;
#pragma unroll 8
        for (int k = 0; k < 128; ++k) {
            ulonglong2 w = w0v[k*64];
            ulonglong2 h = *reinterpret_cast<const ulonglong2*>(h0b + k*IN0_STR); // {r0,r0},{r1,r1}
            a00 = ffma2(w.x, h.x, a00); a01 = ffma2(w.y, h.x, a01);
            a10 = ffma2(w.x, h.y, a10); a11 = ffma2(w.y, h.y, a11);
        }
        float h0v0, h0v1;
        {
            float2 zif = unpk(a00), zgo = unpk(a01);
            float ig = sigap(zif.x), fg = sigap(zif.y);
            float gg = tanhap(zgo.x), og = sigap(zgo.y);
            c0[0] = fg * c0[0] + ig * gg;
            h0v0  = og * tanhap(c0[0]);
        }
        {
            float2 zif = unpk(a10), zgo = unpk(a11);
            float ig = sigap(zif.x), fg = sigap(zif.y);
            float gg = tanhap(zgo.x), og = sigap(zgo.y);
            c0[1] = fg * c0[1] + ig * gg;
            h0v1  = og * tanhap(c0[1]);
        }
        __syncthreads();   // (B) all in0 reads done
        {
            float4 hv = make_float4(h0v0, h0v0, h0v1, h0v1);
            *reinterpret_cast<float4*>(in0 + (64 + u0)*IN0_STR + 4*rg0) = hv;  // recurrent t+1
            *reinterpret_cast<float4*>(in1 + u0*32            + 4*rg0) = hv;  // layer1 input
        }
        if (t + 1 < TSEQ)
            *reinterpret_cast<float4*>(xsts) = make_float4(xr0, xr0, xr1, xr1);
        __syncthreads();   // (C)

        // ================= Layer 1: K=96, 1 row x {if,go} =================
        u64 b0a = bias1.x, b0b = bias1.y;
#pragma unroll 8
        for (int k = 0; k < 96; ++k) {
            ulonglong2 w = w1v[k*32];
            u64 h = *reinterpret_cast<const u64*>(h1b + k*32);  // {r,r}
            b0a = ffma2(w.x, h, b0a);
            b0b = ffma2(w.y, h, b0b);
        }
        float h1val;
        {
            float2 zif = unpk(b0a), zgo = unpk(b0b);
            float ig = sigap(zif.x), fg = sigap(zif.y);
            float gg = tanhap(zgo.x), og = sigap(zgo.y);
            c1v   = fg * c1v + ig * gg;
            h1val = og * tanhap(c1v);
        }
        __syncthreads();   // (D) all in1 reads done
        {
            u64 hv = dup2(h1val);
            *reinterpret_cast<u64*>(in1 + (64 + u1)*32 + 2*r1) = hv;  // recurrent
            *reinterpret_cast<u64*>(in2 + u1*32        + 2*r1) = hv;  // layer2 input
        }
        __syncthreads();   // (E)

        // ================= Layer 2: K=48, 1 row x {if,go} (warps 0-7) =================
        if (l2act) {
            u64 aif = bias2.x, ago = bias2.y;
#pragma unroll 8
            for (int k = 0; k < 48; ++k) {
                ulonglong2 w = w2v[k*16];
                u64 h = *reinterpret_cast<const u64*>(h2b + k*32);  // {h,h}
                aif = ffma2(w.x, h, aif);
                ago = ffma2(w.y, h, ago);
            }
            float2 zif = unpk(aif), zgo = unpk(ago);
            float ig = sigap(zif.x), fg = sigap(zif.y);
            float gg = tanhap(zgo.x), og = sigap(zgo.y);
            c2v = fg * c2v + ig * gg;
            float h2val = og * tanhap(c2v);
            __syncthreads();   // (F) all in2 reads done
            *reinterpret_cast<u64*>(in2 + (32 + u2)*32 + 2*r2) = dup2(h2val);
        } else {
            __syncthreads();   // (F)
        }
        // h2 store ordered before next L2 read by next iteration's syncs
    }
    __syncthreads();

    // ---- Dense head ----
    if (tid < 16) {
        float s = bds[0];
#pragma unroll
        for (int j = 0; j < 16; ++j)
            s += in2[(32 + j)*32 + 2*tid] * wds[j];
        out[row0 + tid] = s;
    }
}

extern "C" void kernel_launch(void* const* d_in, const int* in_sizes, int n_in,
                              void* d_out, int out_size)
{
    (void)in_sizes; (void)n_in; (void)out_size;
    const float* x  = (const float*)d_in[0];
    const float* W0 = (const float*)d_in[1];
    const float* U0 = (const float*)d_in[2];
    const float* b0 = (const float*)d_in[3];
    const float* W1 = (const float*)d_in[4];
    const float* U1 = (const float*)d_in[5];
    const float* b1 = (const float*)d_in[6];
    const float* W2 = (const float*)d_in[7];
    const float* U2 = (const float*)d_in[8];
    const float* b2 = (const float*)d_in[9];
    const float* Wd = (const float*)d_in[10];
    const float* bd = (const float*)d_in[11];
    float* out = (float*)d_out;

    cudaFuncSetAttribute(lstm3_fused_kernel,
                         cudaFuncAttributeMaxDynamicSharedMemorySize, SMEM_BYTES);
    lstm3_fused_kernel<<<NBLK, NT, SMEM_BYTES>>>(
        x, W0, U0, b0, W1, U1, b1, W2, U2, b2, Wd, bd, out);
}

// round 5
// speedup vs baseline: 1.2364x; 1.2364x over previous
#include <cuda_runtime.h>

#define NT    256
#define ROWS  16
#define NBLK  128          // 2048/16
#define TSEQ  256
#define FIN   64

typedef unsigned long long u64;

// ---- smem layout (float offsets) ----
#define WP0_N   (128*64*4)
#define WP1_N   (96*32*4)
#define WP2_N   (48*16*4)
#define WP0_OFF 0
#define WP1_OFF 32768
#define WP2_OFF 45056
#define BP0_OFF 48128
#define BP1_OFF 48384
#define BP2_OFF 48512
#define WDS_OFF 48576
#define BDS_OFF 48592
// state: rows of 32 floats (16 batch rows, row-duplicated), XOR-swizzled 16B slots
#define X_OFF   48608                 // x_t       [64 rows]
#define H0_OFF  (X_OFF  + 64*32)      // h0 double [2][64 rows]
#define H1_OFF  (H0_OFF + 2*64*32)    // h1 double [2][32 rows]
#define H2_OFF  (H1_OFF + 2*32*32)    // h2 double [2][16 rows]
#define SMEM_FLOATS (H2_OFF + 2*16*32)   // 57824
#define SMEM_BYTES  (SMEM_FLOATS * 4)    // 231296
#define STATE_OFF X_OFF
#define STATE_N   (SMEM_FLOATS - X_OFF)  // 9216

__device__ __forceinline__ u64 ffma2(u64 a, u64 b, u64 c) {
    u64 d; asm("fma.rn.f32x2 %0, %1, %2, %3;" : "=l"(d) : "l"(a), "l"(b), "l"(c));
    return d;
}
__device__ __forceinline__ u64 dup2(float x) {
    u64 d; asm("mov.b64 %0, {%1, %1};" : "=l"(d) : "f"(x));
    return d;
}
__device__ __forceinline__ float2 unpk(u64 v) {
    float2 r; asm("mov.b64 {%0, %1}, %2;" : "=f"(r.x), "=f"(r.y) : "l"(v));
    return r;
}
__device__ __forceinline__ float tanhap(float x) {
    float y; asm("tanh.approx.f32 %0, %1;" : "=f"(y) : "f"(x));
    return y;
}
__device__ __forceinline__ float sigap(float x) {
    return fmaf(0.5f, tanhap(0.5f * x), 0.5f);
}

// ---- L0 GEMM segment: 64 k's, 4 rows/thread, batch-4 loads with compile-time swizzle ----
__device__ __forceinline__ void gemmL0(const ulonglong2* __restrict__ w,   // + k*64
                                       const float* __restrict__ base,     // row stride 32
                                       const int* __restrict__ offA,       // offA[xs] = 4*((2rg)^xs)
                                       const int* __restrict__ offB,       // offB[xs] = 4*((2rg+1)^xs)
                                       u64* acc)
{
#pragma unroll
    for (int kk = 0; kk < 64; kk += 8) {
        ulonglong2 wv[4], hA[4], hB[4];
#pragma unroll
        for (int j = 0; j < 4; ++j) {
            const float* row = base + (kk + j) * 32;
            wv[j] = w[(kk + j) * 64];
            hA[j] = *reinterpret_cast<const ulonglong2*>(row + offA[j]);
            hB[j] = *reinterpret_cast<const ulonglong2*>(row + offB[j]);
        }
#pragma unroll
        for (int j = 0; j < 4; ++j) {
            acc[0] = ffma2(wv[j].x, hA[j].x, acc[0]); acc[1] = ffma2(wv[j].y, hA[j].x, acc[1]);
            acc[2] = ffma2(wv[j].x, hA[j].y, acc[2]); acc[3] = ffma2(wv[j].y, hA[j].y, acc[3]);
            acc[4] = ffma2(wv[j].x, hB[j].x, acc[4]); acc[5] = ffma2(wv[j].y, hB[j].x, acc[5]);
            acc[6] = ffma2(wv[j].x, hB[j].y, acc[6]); acc[7] = ffma2(wv[j].y, hB[j].y, acc[7]);
        }
#pragma unroll
        for (int j = 0; j < 4; ++j) {
            const float* row = base + (kk + 4 + j) * 32;
            wv[j] = w[(kk + 4 + j) * 64];
            hA[j] = *reinterpret_cast<const ulonglong2*>(row + offA[4 + j]);
            hB[j] = *reinterpret_cast<const ulonglong2*>(row + offB[4 + j]);
        }
#pragma unroll
        for (int j = 0; j < 4; ++j) {
            acc[0] = ffma2(wv[j].x, hA[j].x, acc[0]); acc[1] = ffma2(wv[j].y, hA[j].x, acc[1]);
            acc[2] = ffma2(wv[j].x, hA[j].y, acc[2]); acc[3] = ffma2(wv[j].y, hA[j].y, acc[3]);
            acc[4] = ffma2(wv[j].x, hB[j].x, acc[4]); acc[5] = ffma2(wv[j].y, hB[j].x, acc[5]);
            acc[6] = ffma2(wv[j].x, hB[j].y, acc[6]); acc[7] = ffma2(wv[j].y, hB[j].y, acc[7]);
        }
    }
}

// ---- L1 GEMM segment: N k's, 2 rows/thread ----
template<int N>
__device__ __forceinline__ void gemmL1(const ulonglong2* __restrict__ w,   // + k*32
                                       const float* __restrict__ base,
                                       const int* __restrict__ off,        // off[xs] = 4*(rg1^xs)
                                       u64* acc)
{
#pragma unroll
    for (int kk = 0; kk < N; kk += 8) {
        ulonglong2 wv[4], hv[4];
#pragma unroll
        for (int j = 0; j < 4; ++j) {
            wv[j] = w[(kk + j) * 32];
            hv[j] = *reinterpret_cast<const ulonglong2*>(base + (kk + j) * 32 + off[j]);
        }
#pragma unroll
        for (int j = 0; j < 4; ++j) {
            acc[0] = ffma2(wv[j].x, hv[j].x, acc[0]); acc[1] = ffma2(wv[j].y, hv[j].x, acc[1]);
            acc[2] = ffma2(wv[j].x, hv[j].y, acc[2]); acc[3] = ffma2(wv[j].y, hv[j].y, acc[3]);
        }
#pragma unroll
        for (int j = 0; j < 4; ++j) {
            wv[j] = w[(kk + 4 + j) * 32];
            hv[j] = *reinterpret_cast<const ulonglong2*>(base + (kk + 4 + j) * 32 + off[4 + j]);
        }
#pragma unroll
        for (int j = 0; j < 4; ++j) {
            acc[0] = ffma2(wv[j].x, hv[j].x, acc[0]); acc[1] = ffma2(wv[j].y, hv[j].x, acc[1]);
            acc[2] = ffma2(wv[j].x, hv[j].y, acc[2]); acc[3] = ffma2(wv[j].y, hv[j].y, acc[3]);
        }
    }
}

// ---- L2 GEMM segment: N k's, 1 row/thread ----
template<int N>
__device__ __forceinline__ void gemmL2(const ulonglong2* __restrict__ w,   // + k*16
                                       const float* __restrict__ base,
                                       const int* __restrict__ off,        // off[xs] = 4*((r2>>1)^xs) + 2*(r2&1)
                                       u64& aif, u64& ago)
{
#pragma unroll
    for (int kk = 0; kk < N; kk += 8) {
        ulonglong2 wv[4]; u64 hv[4];
#pragma unroll
        for (int j = 0; j < 4; ++j) {
            wv[j] = w[(kk + j) * 16];
            hv[j] = *reinterpret_cast<const u64*>(base + (kk + j) * 32 + off[j]);
        }
#pragma unroll
        for (int j = 0; j < 4; ++j) {
            aif = ffma2(wv[j].x, hv[j], aif);
            ago = ffma2(wv[j].y, hv[j], ago);
        }
#pragma unroll
        for (int j = 0; j < 4; ++j) {
            wv[j] = w[(kk + 4 + j) * 16];
            hv[j] = *reinterpret_cast<const u64*>(base + (kk + 4 + j) * 32 + off[4 + j]);
        }
#pragma unroll
        for (int j = 0; j < 4; ++j) {
            aif = ffma2(wv[j].x, hv[j], aif);
            ago = ffma2(wv[j].y, hv[j], ago);
        }
    }
}

__global__ void __launch_bounds__(NT, 1) lstm3_fused_kernel(
    const float* __restrict__ x,
    const float* __restrict__ W0, const float* __restrict__ U0, const float* __restrict__ b0,
    const float* __restrict__ W1, const float* __restrict__ U1, const float* __restrict__ b1,
    const float* __restrict__ W2, const float* __restrict__ U2, const float* __restrict__ b2,
    const float* __restrict__ Wd, const float* __restrict__ bd,
    float* __restrict__ out)
{
    extern __shared__ float sm[];
    const int tid  = threadIdx.x;
    const int row0 = blockIdx.x * ROWS;

    float* wp0 = sm + WP0_OFF;
    float* wp1 = sm + WP1_OFF;
    float* wp2 = sm + WP2_OFF;
    float* bp0 = sm + BP0_OFF;
    float* bp1 = sm + BP1_OFF;
    float* bp2 = sm + BP2_OFF;
    float* wds = sm + WDS_OFF;
    float* bds = sm + BDS_OFF;
    float* xrg = sm + X_OFF;
    float* h0g = sm + H0_OFF;
    float* h1g = sm + H1_OFF;
    float* h2g = sm + H2_OFF;

    // ---- load + rearrange weights: [k][u][g] (gate order i,f,g,o) ----
    for (int idx = tid; idx < WP0_N; idx += NT) {
        int g = idx & 3, u = (idx >> 2) & 63, k = idx >> 8;
        wp0[idx] = (k < 64) ? W0[k*256 + g*64 + u] : U0[(k-64)*256 + g*64 + u];
    }
    for (int idx = tid; idx < WP1_N; idx += NT) {
        int g = idx & 3, u = (idx >> 2) & 31, k = idx >> 7;
        wp1[idx] = (k < 64) ? W1[k*128 + g*32 + u] : U1[(k-64)*128 + g*32 + u];
    }
    for (int idx = tid; idx < WP2_N; idx += NT) {
        int g = idx & 3, u = (idx >> 2) & 15, k = idx >> 6;
        wp2[idx] = (k < 32) ? W2[k*64 + g*16 + u] : U2[(k-32)*64 + g*16 + u];
    }
    if (tid < 256) bp0[tid] = b0[(tid & 3)*64 + (tid >> 2)];
    if (tid < 128) bp1[tid] = b1[(tid & 3)*32 + (tid >> 2)];
    if (tid < 64)  bp2[tid] = b2[(tid & 3)*16 + (tid >> 2)];
    if (tid < 16)  wds[tid] = Wd[tid];
    if (tid == 0)  bds[0]   = bd[0];
    for (int idx = tid; idx < STATE_N; idx += NT) sm[STATE_OFF + idx] = 0.0f;
    __syncthreads();

    // ---- thread mappings (warp-local unit tiling) ----
    const int wrp = tid >> 5, lan = tid & 31;
    const int u0 = (wrp << 3) | (lan & 7), rg0 = lan >> 3;  // 64 units x 4 rowgroups (4 rows)
    const int u1 = (wrp << 2) | (lan & 3), rg1 = lan >> 2;  // 32 units x 8 rowgroups (2 rows)
    const int u2 = (wrp << 1) | (lan & 1), r2  = lan >> 1;  // 16 units x 16 rows

    // swizzle offset tables (compile-time indexed -> registers, zero inner-loop ALU)
    int offA0[8], offB0[8], off1[8], off2[8];
#pragma unroll
    for (int j = 0; j < 8; ++j) {
        offA0[j] = 4 * ((2*rg0)     ^ j);
        offB0[j] = 4 * ((2*rg0 + 1) ^ j);
        off1[j]  = 4 * (rg1 ^ j);
        off2[j]  = 4 * ((r2 >> 1) ^ j) + 2 * (r2 & 1);
    }

    const ulonglong2 bias0 = reinterpret_cast<const ulonglong2*>(bp0)[u0];  // {bi,bf},{bg,bo}
    const ulonglong2 bias1 = reinterpret_cast<const ulonglong2*>(bp1)[u1];
    const ulonglong2 bias2 = reinterpret_cast<const ulonglong2*>(bp2)[u2];

    const ulonglong2* w0v = reinterpret_cast<const ulonglong2*>(wp0) + u0;
    const ulonglong2* w1v = reinterpret_cast<const ulonglong2*>(wp1) + u1;
    const ulonglong2* w2v = reinterpret_cast<const ulonglong2*>(wp2) + u2;

    float c0[4] = {0.f, 0.f, 0.f, 0.f};
    float c1[2] = {0.f, 0.f};
    float c2v   = 0.f;

    // x staging: thread stages rows 4*ra..4*ra+3 of feature f0 (row-dup, swizzled)
    const int f0 = tid & 63;
    const int ra = tid >> 6;
    const size_t xbase = (size_t)(row0 + 4*ra) * (TSEQ * FIN) + f0;
    float* xrow = xrg + f0 * 32;
    const int xs0 = 4 * ((2*ra)     ^ (f0 & 7));
    const int xs1 = 4 * ((2*ra + 1) ^ (f0 & 7));
    float xr[4];
#pragma unroll
    for (int j = 0; j < 4; ++j) xr[j] = x[xbase + (size_t)j * (TSEQ*FIN)];
    *reinterpret_cast<float4*>(xrow + xs0) = make_float4(xr[0], xr[0], xr[1], xr[1]);
    *reinterpret_cast<float4*>(xrow + xs1) = make_float4(xr[2], xr[2], xr[3], xr[3]);
    __syncthreads();

    for (int t = 0; t < TSEQ; ++t) {
        const int p = t & 1;
        const float* h0r = h0g + p * 2048;  float* h0w = h0g + (p ^ 1) * 2048;
        const float* h1r = h1g + p * 1024;  float* h1w = h1g + (p ^ 1) * 1024;
        const float* h2r = h2g + p * 512;   float* h2w = h2g + (p ^ 1) * 512;

        // prefetch x_{t+1} (LDG latency hidden behind L0 GEMM)
        if (t + 1 < TSEQ) {
#pragma unroll
            for (int j = 0; j < 4; ++j)
                xr[j] = x[xbase + (size_t)(t+1)*FIN + (size_t)j * (TSEQ*FIN)];
        }

        // ================= Layer 0: K=128 (x 64 + h0 64) =================
        u64 acc0[8];
#pragma unroll
        for (int r = 0; r < 4; ++r) { acc0[2*r] = bias0.x; acc0[2*r+1] = bias0.y; }
        gemmL0(w0v,          xrg, offA0, offB0, acc0);
        gemmL0(w0v + 64*64,  h0r, offA0, offB0, acc0);
        float h0v[4];
#pragma unroll
        for (int r = 0; r < 4; ++r) {
            float2 zif = unpk(acc0[2*r]), zgo = unpk(acc0[2*r+1]);
            float ig = sigap(zif.x), fg = sigap(zif.y);
            float gg = tanhap(zgo.x), og = sigap(zgo.y);
            c0[r]  = fg * c0[r] + ig * gg;
            h0v[r] = og * tanhap(c0[r]);
        }
        {   // store h0(t) -> h0w (fresh buffer: no WAR)
            float* hb = h0w + u0 * 32;
            const int sx = u0 & 7;
            *reinterpret_cast<float4*>(hb + 4*((2*rg0)     ^ sx)) = make_float4(h0v[0], h0v[0], h0v[1], h0v[1]);
            *reinterpret_cast<float4*>(hb + 4*((2*rg0 + 1) ^ sx)) = make_float4(h0v[2], h0v[2], h0v[3], h0v[3]);
        }
        __syncthreads();   // sync1: publish h0; all x/h0r reads done

        // stage x_{t+1} (x region free now)
        if (t + 1 < TSEQ) {
            *reinterpret_cast<float4*>(xrow + xs0) = make_float4(xr[0], xr[0], xr[1], xr[1]);
            *reinterpret_cast<float4*>(xrow + xs1) = make_float4(xr[2], xr[2], xr[3], xr[3]);
        }

        // ================= Layer 1: K=96 (h0 64 + h1 32) =================
        u64 acc1[4];
        acc1[0] = bias1.x; acc1[1] = bias1.y; acc1[2] = bias1.x; acc1[3] = bias1.y;
        gemmL1<64>(w1v,          h0w, off1, acc1);
        gemmL1<32>(w1v + 64*32,  h1r, off1, acc1);
        float h1v[2];
#pragma unroll
        for (int r = 0; r < 2; ++r) {
            float2 zif = unpk(acc1[2*r]), zgo = unpk(acc1[2*r+1]);
            float ig = sigap(zif.x), fg = sigap(zif.y);
            float gg = tanhap(zgo.x), og = sigap(zgo.y);
            c1[r]  = fg * c1[r] + ig * gg;
            h1v[r] = og * tanhap(c1[r]);
        }
        *reinterpret_cast<float4*>(h1w + u1*32 + 4*(rg1 ^ (u1 & 7))) =
            make_float4(h1v[0], h1v[0], h1v[1], h1v[1]);
        __syncthreads();   // sync2: publish h1

        // ================= Layer 2: K=48 (h1 32 + h2 16) =================
        u64 aif = bias2.x, ago = bias2.y;
        gemmL2<32>(w2v,          h1w, off2, aif, ago);
        gemmL2<16>(w2v + 32*16,  h2r, off2, aif, ago);
        {
            float2 zif = unpk(aif), zgo = unpk(ago);
            float ig = sigap(zif.x), fg = sigap(zif.y);
            float gg = tanhap(zgo.x), og = sigap(zgo.y);
            c2v = fg * c2v + ig * gg;
            float h2val = og * tanhap(c2v);
            *reinterpret_cast<u64*>(h2w + u2*32 + 4*((r2 >> 1) ^ (u2 & 7)) + 2*(r2 & 1)) = dup2(h2val);
        }
        __syncthreads();   // sync3: publish h2 (+ x for next step)
    }

    // ---- Dense head: final h2 lives in buffer 0 (t=255 -> write parity 0) ----
    if (tid < 16) {
        const float* h2f = h2g;   // buffer 0
        float s = bds[0];
#pragma unroll
        for (int j = 0; j < 16; ++j)
            s += h2f[j*32 + 4*((tid >> 1) ^ (j & 7)) + 2*(tid & 1)] * wds[j];
        out[row0 + tid] = s;
    }
}

extern "C" void kernel_launch(void* const* d_in, const int* in_sizes, int n_in,
                              void* d_out, int out_size)
{
    (void)in_sizes; (void)n_in; (void)out_size;
    const float* x  = (const float*)d_in[0];
    const float* W0 = (const float*)d_in[1];
    const float* U0 = (const float*)d_in[2];
    const float* b0 = (const float*)d_in[3];
    const float* W1 = (const float*)d_in[4];
    const float* U1 = (const float*)d_in[5];
    const float* b1 = (const float*)d_in[6];
    const float* W2 = (const float*)d_in[7];
    const float* U2 = (const float*)d_in[8];
    const float* b2 = (const float*)d_in[9];
    const float* Wd = (const float*)d_in[10];
    const float* bd = (const float*)d_in[11];
    float* out = (float*)d_out;

    cudaFuncSetAttribute(lstm3_fused_kernel,
                         cudaFuncAttributeMaxDynamicSharedMemorySize, SMEM_BYTES);
    lstm3_fused_kernel<<<NBLK, NT, SMEM_BYTES>>>(
        x, W0, U0, b0, W1, U1, b1, W2, U2, b2, Wd, bd, out);
}

// round 6
// speedup vs baseline: 1.3265x; 1.0729x over previous
#include <cuda_runtime.h>
#include <cstdint>

#define NT    256
#define ROWS  16
#define NBLK  128          // 2048/16
#define TSEQ  256
#define FIN   64

typedef unsigned long long u64;

// 512MB scratch: xz[bx][t][i2][tid][4 floats]  (per-thread accumulator layout)
__device__ float g_lstm_xz_scratch[134217728];

// ---------------- phase-2 smem layout (float offsets) ----------------
#define WP0_N   (64*64*4)             // U0 rearranged [k][u][g]
#define WP1_N   (96*32*4)
#define WP2_N   (48*16*4)
#define WP0_OFF 0
#define WP1_OFF 16384
#define WP2_OFF 28672
#define BP1_OFF 31744
#define BP2_OFF 31872
#define WDS_OFF 31936
#define BDS_OFF 31952
#define XZB_OFF 31968                 // 16B aligned; double buffer 2x4096
#define H0_OFF  (XZB_OFF + 2*4096)    // 40160 : h0 double [2][64*32]
#define H1_OFF  (H0_OFF + 2*2048)     // 44256 : h1 double [2][32*32]
#define H2_OFF  (H1_OFF + 2*1024)     // 46304 : h2 double [2][16*32]
#define SMEM_FLOATS (H2_OFF + 2*512)  // 47328
#define SMEM_BYTES  (SMEM_FLOATS*4)   // 189312

// ---------------- phase-1 smem layout ----------------
#define P1_WP   0                     // W0 [64][64][4] = 16384
#define P1_BP   16384                 // 256
#define P1_XS0  16640                 // 2048
#define P1_XS1  18688                 // 2048
#define P1_FLOATS 20736
#define P1_BYTES  (P1_FLOATS*4)       // 82944

__device__ __forceinline__ u64 ffma2(u64 a, u64 b, u64 c) {
    u64 d; asm("fma.rn.f32x2 %0, %1, %2, %3;" : "=l"(d) : "l"(a), "l"(b), "l"(c));
    return d;
}
__device__ __forceinline__ u64 dup2(float x) {
    u64 d; asm("mov.b64 %0, {%1, %1};" : "=l"(d) : "f"(x));
    return d;
}
__device__ __forceinline__ float2 unpk(u64 v) {
    float2 r; asm("mov.b64 {%0, %1}, %2;" : "=f"(r.x), "=f"(r.y) : "l"(v));
    return r;
}
__device__ __forceinline__ float tanhap(float x) {
    float y; asm("tanh.approx.f32 %0, %1;" : "=f"(y) : "f"(x));
    return y;
}
__device__ __forceinline__ float sigap(float x) {
    return fmaf(0.5f, tanhap(0.5f * x), 0.5f);
}
__device__ __forceinline__ void cpasync16(uint32_t saddr, const float* g) {
    asm volatile("cp.async.ca.shared.global [%0], [%1], 16;" :: "r"(saddr), "l"(g));
}

// ================== PHASE 1: xz = x@W0 + b0 for all (b,t) ==================
__global__ void __launch_bounds__(NT, 2) xz_kernel(
    const float* __restrict__ x,
    const float* __restrict__ W0,
    const float* __restrict__ b0)
{
    extern __shared__ float sm[];
    float* wp  = sm + P1_WP;
    float* bp  = sm + P1_BP;
    float* xs0 = sm + P1_XS0;
    float* xs1 = sm + P1_XS1;
    const int tid = threadIdx.x;

    for (int idx = tid; idx < 64*64*4; idx += NT) {
        int g = idx & 3, u = (idx >> 2) & 63, k = idx >> 8;
        wp[idx] = W0[k*256 + g*64 + u];
    }
    if (tid < 256) bp[tid] = b0[(tid & 3)*64 + (tid >> 2)];
    __syncthreads();

    const int wrp = tid >> 5, lan = tid & 31;
    const int u0 = (wrp << 3) | (lan & 7), rg0 = lan >> 3;
    int offA[8], offB[8];
#pragma unroll
    for (int j = 0; j < 8; ++j) {
        offA[j] = 4 * ((2*rg0)     ^ j);
        offB[j] = 4 * ((2*rg0 + 1) ^ j);
    }
    const ulonglong2 bias = reinterpret_cast<const ulonglong2*>(bp)[u0];
    const ulonglong2* wv  = reinterpret_cast<const ulonglong2*>(wp) + u0;

    // x staging mapping
    const int f0 = tid & 63;
    const int ra = tid >> 6;
    const int row0  = blockIdx.x * ROWS;
    const int tbase = blockIdx.y * 32;
    const size_t xrow = (size_t)(row0 + 4*ra) * (TSEQ*FIN) + f0;
    float* s0 = xs0 + f0*32;
    float* s1 = xs1 + f0*32;
    const int sl0 = 4*((2*ra)     ^ (f0 & 7));
    const int sl1 = 4*((2*ra + 1) ^ (f0 & 7));

    float xr[8];
#pragma unroll
    for (int j = 0; j < 4; ++j) {
        xr[j]   = x[xrow + (size_t)j*(TSEQ*FIN) + (size_t)tbase*FIN];
        xr[4+j] = x[xrow + (size_t)j*(TSEQ*FIN) + (size_t)(tbase+1)*FIN];
    }

    for (int tp = 0; tp < 16; ++tp) {
        const int t0 = tbase + 2*tp;
        __syncthreads();   // prev gemm reads done
        *reinterpret_cast<float4*>(s0 + sl0) = make_float4(xr[0], xr[0], xr[1], xr[1]);
        *reinterpret_cast<float4*>(s0 + sl1) = make_float4(xr[2], xr[2], xr[3], xr[3]);
        *reinterpret_cast<float4*>(s1 + sl0) = make_float4(xr[4], xr[4], xr[5], xr[5]);
        *reinterpret_cast<float4*>(s1 + sl1) = make_float4(xr[6], xr[6], xr[7], xr[7]);
        __syncthreads();

        // prefetch next pair's x (overlaps gemm)
        if (tp < 15) {
#pragma unroll
            for (int j = 0; j < 4; ++j) {
                xr[j]   = x[xrow + (size_t)j*(TSEQ*FIN) + (size_t)(t0+2)*FIN];
                xr[4+j] = x[xrow + (size_t)j*(TSEQ*FIN) + (size_t)(t0+3)*FIN];
            }
        }

        u64 A[8], B[8];
#pragma unroll
        for (int r = 0; r < 4; ++r) {
            A[2*r] = bias.x; A[2*r+1] = bias.y;
            B[2*r] = bias.x; B[2*r+1] = bias.y;
        }
#pragma unroll 8
        for (int k = 0; k < 64; ++k) {
            const int j = k & 7;
            ulonglong2 w  = wv[k*64];
            ulonglong2 a0 = *reinterpret_cast<const ulonglong2*>(xs0 + k*32 + offA[j]);
            ulonglong2 b0v= *reinterpret_cast<const ulonglong2*>(xs0 + k*32 + offB[j]);
            ulonglong2 a1 = *reinterpret_cast<const ulonglong2*>(xs1 + k*32 + offA[j]);
            ulonglong2 b1v= *reinterpret_cast<const ulonglong2*>(xs1 + k*32 + offB[j]);
            A[0]=ffma2(w.x,a0.x,A[0]);  A[1]=ffma2(w.y,a0.x,A[1]);
            A[2]=ffma2(w.x,a0.y,A[2]);  A[3]=ffma2(w.y,a0.y,A[3]);
            A[4]=ffma2(w.x,b0v.x,A[4]); A[5]=ffma2(w.y,b0v.x,A[5]);
            A[6]=ffma2(w.x,b0v.y,A[6]); A[7]=ffma2(w.y,b0v.y,A[7]);
            B[0]=ffma2(w.x,a1.x,B[0]);  B[1]=ffma2(w.y,a1.x,B[1]);
            B[2]=ffma2(w.x,a1.y,B[2]);  B[3]=ffma2(w.y,a1.y,B[3]);
            B[4]=ffma2(w.x,b1v.x,B[4]); B[5]=ffma2(w.y,b1v.x,B[5]);
            B[6]=ffma2(w.x,b1v.y,B[6]); B[7]=ffma2(w.y,b1v.y,B[7]);
        }
        // store in per-thread accumulator layout: [bx][t][i2][tid][4]
        float* g0 = g_lstm_xz_scratch + ((size_t)(blockIdx.x*256 + t0)) * 4096 + tid*4;
        float* g1 = g0 + 4096;
#pragma unroll
        for (int i2 = 0; i2 < 4; ++i2) {
            *reinterpret_cast<ulonglong2*>(g0 + i2*1024) = make_ulonglong2(A[2*i2], A[2*i2+1]);
            *reinterpret_cast<ulonglong2*>(g1 + i2*1024) = make_ulonglong2(B[2*i2], B[2*i2+1]);
        }
    }
}

// ---- L0 GEMM segment (K=64, 4 rows/thread) ----
__device__ __forceinline__ void gemmL0(const ulonglong2* __restrict__ w,
                                       const float* __restrict__ base,
                                       const int* __restrict__ offA,
                                       const int* __restrict__ offB,
                                       u64* acc)
{
#pragma unroll
    for (int kk = 0; kk < 64; kk += 8) {
        ulonglong2 wv[4], hA[4], hB[4];
#pragma unroll
        for (int j = 0; j < 4; ++j) {
            const float* row = base + (kk + j) * 32;
            wv[j] = w[(kk + j) * 64];
            hA[j] = *reinterpret_cast<const ulonglong2*>(row + offA[j]);
            hB[j] = *reinterpret_cast<const ulonglong2*>(row + offB[j]);
        }
#pragma unroll
        for (int j = 0; j < 4; ++j) {
            acc[0] = ffma2(wv[j].x, hA[j].x, acc[0]); acc[1] = ffma2(wv[j].y, hA[j].x, acc[1]);
            acc[2] = ffma2(wv[j].x, hA[j].y, acc[2]); acc[3] = ffma2(wv[j].y, hA[j].y, acc[3]);
            acc[4] = ffma2(wv[j].x, hB[j].x, acc[4]); acc[5] = ffma2(wv[j].y, hB[j].x, acc[5]);
            acc[6] = ffma2(wv[j].x, hB[j].y, acc[6]); acc[7] = ffma2(wv[j].y, hB[j].y, acc[7]);
        }
#pragma unroll
        for (int j = 0; j < 4; ++j) {
            const float* row = base + (kk + 4 + j) * 32;
            wv[j] = w[(kk + 4 + j) * 64];
            hA[j] = *reinterpret_cast<const ulonglong2*>(row + offA[4 + j]);
            hB[j] = *reinterpret_cast<const ulonglong2*>(row + offB[4 + j]);
        }
#pragma unroll
        for (int j = 0; j < 4; ++j) {
            acc[0] = ffma2(wv[j].x, hA[j].x, acc[0]); acc[1] = ffma2(wv[j].y, hA[j].x, acc[1]);
            acc[2] = ffma2(wv[j].x, hA[j].y, acc[2]); acc[3] = ffma2(wv[j].y, hA[j].y, acc[3]);
            acc[4] = ffma2(wv[j].x, hB[j].x, acc[4]); acc[5] = ffma2(wv[j].y, hB[j].x, acc[5]);
            acc[6] = ffma2(wv[j].x, hB[j].y, acc[6]); acc[7] = ffma2(wv[j].y, hB[j].y, acc[7]);
        }
    }
}

template<int N>
__device__ __forceinline__ void gemmL1(const ulonglong2* __restrict__ w,
                                       const float* __restrict__ base,
                                       const int* __restrict__ off,
                                       u64* acc)
{
#pragma unroll
    for (int kk = 0; kk < N; kk += 8) {
        ulonglong2 wv[4], hv[4];
#pragma unroll
        for (int j = 0; j < 4; ++j) {
            wv[j] = w[(kk + j) * 32];
            hv[j] = *reinterpret_cast<const ulonglong2*>(base + (kk + j) * 32 + off[j]);
        }
#pragma unroll
        for (int j = 0; j < 4; ++j) {
            acc[0] = ffma2(wv[j].x, hv[j].x, acc[0]); acc[1] = ffma2(wv[j].y, hv[j].x, acc[1]);
            acc[2] = ffma2(wv[j].x, hv[j].y, acc[2]); acc[3] = ffma2(wv[j].y, hv[j].y, acc[3]);
        }
#pragma unroll
        for (int j = 0; j < 4; ++j) {
            wv[j] = w[(kk + 4 + j) * 32];
            hv[j] = *reinterpret_cast<const ulonglong2*>(base + (kk + 4 + j) * 32 + off[4 + j]);
        }
#pragma unroll
        for (int j = 0; j < 4; ++j) {
            acc[0] = ffma2(wv[j].x, hv[j].x, acc[0]); acc[1] = ffma2(wv[j].y, hv[j].x, acc[1]);
            acc[2] = ffma2(wv[j].x, hv[j].y, acc[2]); acc[3] = ffma2(wv[j].y, hv[j].y, acc[3]);
        }
    }
}

template<int N>
__device__ __forceinline__ void gemmL2(const ulonglong2* __restrict__ w,
                                       const float* __restrict__ base,
                                       const int* __restrict__ off,
                                       u64& aif, u64& ago)
{
#pragma unroll
    for (int kk = 0; kk < N; kk += 8) {
        ulonglong2 wv[4]; u64 hv[4];
#pragma unroll
        for (int j = 0; j < 4; ++j) {
            wv[j] = w[(kk + j) * 16];
            hv[j] = *reinterpret_cast<const u64*>(base + (kk + j) * 32 + off[j]);
        }
#pragma unroll
        for (int j = 0; j < 4; ++j) {
            aif = ffma2(wv[j].x, hv[j], aif);
            ago = ffma2(wv[j].y, hv[j], ago);
        }
#pragma unroll
        for (int j = 0; j < 4; ++j) {
            wv[j] = w[(kk + 4 + j) * 16];
            hv[j] = *reinterpret_cast<const u64*>(base + (kk + 4 + j) * 32 + off[4 + j]);
        }
#pragma unroll
        for (int j = 0; j < 4; ++j) {
            aif = ffma2(wv[j].x, hv[j], aif);
            ago = ffma2(wv[j].y, hv[j], ago);
        }
    }
}

// ================== PHASE 2: recurrent loop ==================
__global__ void __launch_bounds__(NT, 1) lstm3_rec_kernel(
    const float* __restrict__ U0,
    const float* __restrict__ W1, const float* __restrict__ U1, const float* __restrict__ b1,
    const float* __restrict__ W2, const float* __restrict__ U2, const float* __restrict__ b2,
    const float* __restrict__ Wd, const float* __restrict__ bd,
    float* __restrict__ out)
{
    extern __shared__ float sm[];
    const int tid = threadIdx.x;
    const int bx  = blockIdx.x;
    const int row0 = bx * ROWS;

    float* wp0 = sm + WP0_OFF;
    float* wp1 = sm + WP1_OFF;
    float* wp2 = sm + WP2_OFF;
    float* bp1 = sm + BP1_OFF;
    float* bp2 = sm + BP2_OFF;
    float* wds = sm + WDS_OFF;
    float* bds = sm + BDS_OFF;
    float* xzb = sm + XZB_OFF;
    float* h0g = sm + H0_OFF;
    float* h1g = sm + H1_OFF;
    float* h2g = sm + H2_OFF;

    // prefetch xz[t=0] into buffer 0 (own tid slots)
    {
        const float* gp = g_lstm_xz_scratch + ((size_t)bx * 256) * 4096 + tid*4;
        uint32_t sa = (uint32_t)__cvta_generic_to_shared(xzb + tid*4);
#pragma unroll
        for (int i2 = 0; i2 < 4; ++i2)
            cpasync16(sa + i2*1024*4, gp + i2*1024);
        asm volatile("cp.async.commit_group;" ::: "memory");
    }

    // ---- load + rearrange weights ----
    for (int idx = tid; idx < WP0_N; idx += NT) {
        int g = idx & 3, u = (idx >> 2) & 63, k = idx >> 8;   // k 0..63
        wp0[idx] = U0[k*256 + g*64 + u];
    }
    for (int idx = tid; idx < WP1_N; idx += NT) {
        int g = idx & 3, u = (idx >> 2) & 31, k = idx >> 7;
        wp1[idx] = (k < 64) ? W1[k*128 + g*32 + u] : U1[(k-64)*128 + g*32 + u];
    }
    for (int idx = tid; idx < WP2_N; idx += NT) {
        int g = idx & 3, u = (idx >> 2) & 15, k = idx >> 6;
        wp2[idx] = (k < 32) ? W2[k*64 + g*16 + u] : U2[(k-32)*64 + g*16 + u];
    }
    if (tid < 128) bp1[tid] = b1[(tid & 3)*32 + (tid >> 2)];
    if (tid < 64)  bp2[tid] = b2[(tid & 3)*16 + (tid >> 2)];
    if (tid < 16)  wds[tid] = Wd[tid];
    if (tid == 0)  bds[0]   = bd[0];
    for (int idx = tid; idx < 2*2048 + 2*1024 + 2*512; idx += NT) h0g[idx] = 0.0f;  // h0,h1,h2 contiguous
    asm volatile("cp.async.wait_group 0;" ::: "memory");
    __syncthreads();

    // ---- thread mappings ----
    const int wrp = tid >> 5, lan = tid & 31;
    const int u0 = (wrp << 3) | (lan & 7), rg0 = lan >> 3;
    const int u1 = (wrp << 2) | (lan & 3), rg1 = lan >> 2;
    const int u2 = (wrp << 1) | (lan & 1), r2  = lan >> 1;

    int offA0[8], offB0[8], off1[8], off2[8];
#pragma unroll
    for (int j = 0; j < 8; ++j) {
        offA0[j] = 4 * ((2*rg0)     ^ j);
        offB0[j] = 4 * ((2*rg0 + 1) ^ j);
        off1[j]  = 4 * (rg1 ^ j);
        off2[j]  = 4 * ((r2 >> 1) ^ j) + 2 * (r2 & 1);
    }

    const ulonglong2 bias1 = reinterpret_cast<const ulonglong2*>(bp1)[u1];
    const ulonglong2 bias2 = reinterpret_cast<const ulonglong2*>(bp2)[u2];

    const ulonglong2* w0v = reinterpret_cast<const ulonglong2*>(wp0) + u0;
    const ulonglong2* w1v = reinterpret_cast<const ulonglong2*>(wp1) + u1;
    const ulonglong2* w2v = reinterpret_cast<const ulonglong2*>(wp2) + u2;

    float c0[4] = {0.f, 0.f, 0.f, 0.f};
    float c1[2] = {0.f, 0.f};
    float c2v   = 0.f;

    const uint32_t xz_sa = (uint32_t)__cvta_generic_to_shared(xzb + tid*4);

    for (int t = 0; t < TSEQ; ++t) {
        const int p = t & 1;
        const float* h0r = h0g + p * 2048;  float* h0w = h0g + (p ^ 1) * 2048;
        const float* h1r = h1g + p * 1024;  float* h1w = h1g + (p ^ 1) * 1024;
        const float* h2r = h2g + p * 512;   float* h2w = h2g + (p ^ 1) * 512;
        const float* xzr = xzb + p * 4096;

        // prefetch xz[t+1] into the other buffer (self-slots; waited at end of step)
        if (t + 1 < TSEQ) {
            const float* gp = g_lstm_xz_scratch + ((size_t)(bx*256 + t + 1)) * 4096 + tid*4;
            uint32_t sa = xz_sa + (p ^ 1) * 4096 * 4;
#pragma unroll
            for (int i2 = 0; i2 < 4; ++i2)
                cpasync16(sa + i2*1024*4, gp + i2*1024);
            asm volatile("cp.async.commit_group;" ::: "memory");
        }

        // ================= Layer 0: acc init from xz, K=64 over h0 =================
        u64 acc0[8];
#pragma unroll
        for (int i2 = 0; i2 < 4; ++i2) {
            ulonglong2 v = *reinterpret_cast<const ulonglong2*>(xzr + i2*1024 + tid*4);
            acc0[2*i2] = v.x; acc0[2*i2+1] = v.y;
        }
        gemmL0(w0v, h0r, offA0, offB0, acc0);
        float h0v[4];
#pragma unroll
        for (int r = 0; r < 4; ++r) {
            float2 zif = unpk(acc0[2*r]), zgo = unpk(acc0[2*r+1]);
            float ig = sigap(zif.x), fg = sigap(zif.y);
            float gg = tanhap(zgo.x), og = sigap(zgo.y);
            c0[r]  = fg * c0[r] + ig * gg;
            h0v[r] = og * tanhap(c0[r]);
        }
        {
            float* hb = h0w + u0 * 32;
            const int sx = u0 & 7;
            *reinterpret_cast<float4*>(hb + 4*((2*rg0)     ^ sx)) = make_float4(h0v[0], h0v[0], h0v[1], h0v[1]);
            *reinterpret_cast<float4*>(hb + 4*((2*rg0 + 1) ^ sx)) = make_float4(h0v[2], h0v[2], h0v[3], h0v[3]);
        }
        __syncthreads();   // sync1: publish h0

        // ================= Layer 1: K=96 (h0 64 + h1 32) =================
        u64 acc1[4];
        acc1[0] = bias1.x; acc1[1] = bias1.y; acc1[2] = bias1.x; acc1[3] = bias1.y;
        gemmL1<64>(w1v,         h0w, off1, acc1);
        gemmL1<32>(w1v + 64*32, h1r, off1, acc1);
        float h1v[2];
#pragma unroll
        for (int r = 0; r < 2; ++r) {
            float2 zif = unpk(acc1[2*r]), zgo = unpk(acc1[2*r+1]);
            float ig = sigap(zif.x), fg = sigap(zif.y);
            float gg = tanhap(zgo.x), og = sigap(zgo.y);
            c1[r]  = fg * c1[r] + ig * gg;
            h1v[r] = og * tanhap(c1[r]);
        }
        *reinterpret_cast<float4*>(h1w + u1*32 + 4*(rg1 ^ (u1 & 7))) =
            make_float4(h1v[0], h1v[0], h1v[1], h1v[1]);
        __syncthreads();   // sync2: publish h1

        // ================= Layer 2: K=48 (h1 32 + h2 16) =================
        u64 aif = bias2.x, ago = bias2.y;
        gemmL2<32>(w2v,         h1w, off2, aif, ago);
        gemmL2<16>(w2v + 32*16, h2r, off2, aif, ago);
        {
            float2 zif = unpk(aif), zgo = unpk(ago);
            float ig = sigap(zif.x), fg = sigap(zif.y);
            float gg = tanhap(zgo.x), og = sigap(zgo.y);
            c2v = fg * c2v + ig * gg;
            float h2val = og * tanhap(c2v);
            *reinterpret_cast<u64*>(h2w + u2*32 + 4*((r2 >> 1) ^ (u2 & 7)) + 2*(r2 & 1)) = dup2(h2val);
        }
        asm volatile("cp.async.wait_group 0;" ::: "memory");
        __syncthreads();   // sync3: publish h2; xz[t+1] resident
    }

    // ---- Dense head: final h2 in buffer 0 (t=255 writes parity 0) ----
    if (tid < 16) {
        const float* h2f = h2g;
        float s = bds[0];
#pragma unroll
        for (int j = 0; j < 16; ++j)
            s += h2f[j*32 + 4*((tid >> 1) ^ (j & 7)) + 2*(tid & 1)] * wds[j];
        out[row0 + tid] = s;
    }
}

extern "C" void kernel_launch(void* const* d_in, const int* in_sizes, int n_in,
                              void* d_out, int out_size)
{
    (void)in_sizes; (void)n_in; (void)out_size;
    const float* x  = (const float*)d_in[0];
    const float* W0 = (const float*)d_in[1];
    const float* U0 = (const float*)d_in[2];
    const float* b0 = (const float*)d_in[3];
    const float* W1 = (const float*)d_in[4];
    const float* U1 = (const float*)d_in[5];
    const float* b1 = (const float*)d_in[6];
    const float* W2 = (const float*)d_in[7];
    const float* U2 = (const float*)d_in[8];
    const float* b2 = (const float*)d_in[9];
    const float* Wd = (const float*)d_in[10];
    const float* bd = (const float*)d_in[11];
    float* out = (float*)d_out;

    cudaFuncSetAttribute(xz_kernel,
                         cudaFuncAttributeMaxDynamicSharedMemorySize, P1_BYTES);
    cudaFuncSetAttribute(lstm3_rec_kernel,
                         cudaFuncAttributeMaxDynamicSharedMemorySize, SMEM_BYTES);

    xz_kernel<<<dim3(NBLK, 8), NT, P1_BYTES>>>(x, W0, b0);
    lstm3_rec_kernel<<<NBLK, NT, SMEM_BYTES>>>(
        U0, W1, U1, b1, W2, U2, b2, Wd, bd, out);
}

// round 7
// speedup vs baseline: 1.3399x; 1.0101x over previous
#include <cuda_runtime.h>
#include <cstdint>

#define NT    256
#define ROWS  16
#define NBLK  128          // 2048/16
#define TSEQ  256
#define FIN   64

typedef unsigned long long u64;

// 512MB scratch: xz[bx][t][i2][tid][4 floats]  (per-thread accumulator layout)
__device__ float g_lstm_xz_scratch[134217728];

// ---------------- phase-2 smem layout (float offsets) ----------------
#define WP0_N   (64*64*4)             // U0 rearranged [k][u][g]
#define WP1_N   (96*32*4)
#define WP2_N   (48*16*4)
#define WP0_OFF 0
#define WP1_OFF 16384
#define WP2_OFF 28672
#define BP1_OFF 31744
#define BP2_OFF 31872
#define WDS_OFF 31936
#define BDS_OFF 31952
#define XZB_OFF 31968                 // double buffer 2x4096
#define H0_OFF  (XZB_OFF + 2*4096)    // h0 double [2][64*32]
#define H1_OFF  (H0_OFF + 2*2048)     // h1 double [2][32*32]
#define H2_OFF  (H1_OFF + 2*1024)     // h2 double [2][16*32]
#define SMEM_FLOATS (H2_OFF + 2*512)  // 47328
#define SMEM_BYTES  (SMEM_FLOATS*4)   // 189312

// ---------------- phase-1 smem layout ----------------
#define P1_WP   0
#define P1_BP   16384
#define P1_XS0  16640
#define P1_XS1  18688
#define P1_FLOATS 20736
#define P1_BYTES  (P1_FLOATS*4)

__device__ __forceinline__ u64 ffma2(u64 a, u64 b, u64 c) {
    u64 d; asm("fma.rn.f32x2 %0, %1, %2, %3;" : "=l"(d) : "l"(a), "l"(b), "l"(c));
    return d;
}
__device__ __forceinline__ u64 dup2(float x) {
    u64 d; asm("mov.b64 %0, {%1, %1};" : "=l"(d) : "f"(x));
    return d;
}
__device__ __forceinline__ float2 unpk(u64 v) {
    float2 r; asm("mov.b64 {%0, %1}, %2;" : "=f"(r.x), "=f"(r.y) : "l"(v));
    return r;
}
__device__ __forceinline__ float tanhap(float x) {
    float y; asm("tanh.approx.f32 %0, %1;" : "=f"(y) : "f"(x));
    return y;
}
__device__ __forceinline__ float sigap(float x) {
    return fmaf(0.5f, tanhap(0.5f * x), 0.5f);
}
__device__ __forceinline__ void cpasync16(uint32_t saddr, const float* g) {
    asm volatile("cp.async.ca.shared.global [%0], [%1], 16;" :: "r"(saddr), "l"(g));
}

// ================== PHASE 1: xz = x@W0 + b0 for all (b,t) ==================
__global__ void __launch_bounds__(NT, 2) xz_kernel(
    const float* __restrict__ x,
    const float* __restrict__ W0,
    const float* __restrict__ b0)
{
    extern __shared__ float sm[];
    float* wp  = sm + P1_WP;
    float* bp  = sm + P1_BP;
    float* xs0 = sm + P1_XS0;
    float* xs1 = sm + P1_XS1;
    const int tid = threadIdx.x;

    for (int idx = tid; idx < 64*64*4; idx += NT) {
        int g = idx & 3, u = (idx >> 2) & 63, k = idx >> 8;
        wp[idx] = W0[k*256 + g*64 + u];
    }
    if (tid < 256) bp[tid] = b0[(tid & 3)*64 + (tid >> 2)];
    __syncthreads();

    const int wrp = tid >> 5, lan = tid & 31;
    const int u0 = (wrp << 3) | (lan & 7), rg0 = lan >> 3;
    int offA[8], offB[8];
#pragma unroll
    for (int j = 0; j < 8; ++j) {
        offA[j] = 4 * ((2*rg0)     ^ j);
        offB[j] = 4 * ((2*rg0 + 1) ^ j);
    }
    const ulonglong2 bias = reinterpret_cast<const ulonglong2*>(bp)[u0];
    const ulonglong2* wv  = reinterpret_cast<const ulonglong2*>(wp) + u0;

    const int f0 = tid & 63;
    const int ra = tid >> 6;
    const int row0  = blockIdx.x * ROWS;
    const int tbase = blockIdx.y * 32;
    const size_t xrow = (size_t)(row0 + 4*ra) * (TSEQ*FIN) + f0;
    float* s0 = xs0 + f0*32;
    float* s1 = xs1 + f0*32;
    const int sl0 = 4*((2*ra)     ^ (f0 & 7));
    const int sl1 = 4*((2*ra + 1) ^ (f0 & 7));

    float xr[8];
#pragma unroll
    for (int j = 0; j < 4; ++j) {
        xr[j]   = x[xrow + (size_t)j*(TSEQ*FIN) + (size_t)tbase*FIN];
        xr[4+j] = x[xrow + (size_t)j*(TSEQ*FIN) + (size_t)(tbase+1)*FIN];
    }

    for (int tp = 0; tp < 16; ++tp) {
        const int t0 = tbase + 2*tp;
        __syncthreads();
        *reinterpret_cast<float4*>(s0 + sl0) = make_float4(xr[0], xr[0], xr[1], xr[1]);
        *reinterpret_cast<float4*>(s0 + sl1) = make_float4(xr[2], xr[2], xr[3], xr[3]);
        *reinterpret_cast<float4*>(s1 + sl0) = make_float4(xr[4], xr[4], xr[5], xr[5]);
        *reinterpret_cast<float4*>(s1 + sl1) = make_float4(xr[6], xr[6], xr[7], xr[7]);
        __syncthreads();

        if (tp < 15) {
#pragma unroll
            for (int j = 0; j < 4; ++j) {
                xr[j]   = x[xrow + (size_t)j*(TSEQ*FIN) + (size_t)(t0+2)*FIN];
                xr[4+j] = x[xrow + (size_t)j*(TSEQ*FIN) + (size_t)(t0+3)*FIN];
            }
        }

        u64 A[8], B[8];
#pragma unroll
        for (int r = 0; r < 4; ++r) {
            A[2*r] = bias.x; A[2*r+1] = bias.y;
            B[2*r] = bias.x; B[2*r+1] = bias.y;
        }
#pragma unroll 8
        for (int k = 0; k < 64; ++k) {
            const int j = k & 7;
            ulonglong2 w  = wv[k*64];
            ulonglong2 a0 = *reinterpret_cast<const ulonglong2*>(xs0 + k*32 + offA[j]);
            ulonglong2 b0v= *reinterpret_cast<const ulonglong2*>(xs0 + k*32 + offB[j]);
            ulonglong2 a1 = *reinterpret_cast<const ulonglong2*>(xs1 + k*32 + offA[j]);
            ulonglong2 b1v= *reinterpret_cast<const ulonglong2*>(xs1 + k*32 + offB[j]);
            A[0]=ffma2(w.x,a0.x,A[0]);  A[1]=ffma2(w.y,a0.x,A[1]);
            A[2]=ffma2(w.x,a0.y,A[2]);  A[3]=ffma2(w.y,a0.y,A[3]);
            A[4]=ffma2(w.x,b0v.x,A[4]); A[5]=ffma2(w.y,b0v.x,A[5]);
            A[6]=ffma2(w.x,b0v.y,A[6]); A[7]=ffma2(w.y,b0v.y,A[7]);
            B[0]=ffma2(w.x,a1.x,B[0]);  B[1]=ffma2(w.y,a1.x,B[1]);
            B[2]=ffma2(w.x,a1.y,B[2]);  B[3]=ffma2(w.y,a1.y,B[3]);
            B[4]=ffma2(w.x,b1v.x,B[4]); B[5]=ffma2(w.y,b1v.x,B[5]);
            B[6]=ffma2(w.x,b1v.y,B[6]); B[7]=ffma2(w.y,b1v.y,B[7]);
        }
        float* g0 = g_lstm_xz_scratch + ((size_t)(blockIdx.x*256 + t0)) * 4096 + tid*4;
        float* g1 = g0 + 4096;
#pragma unroll
        for (int i2 = 0; i2 < 4; ++i2) {
            *reinterpret_cast<ulonglong2*>(g0 + i2*1024) = make_ulonglong2(A[2*i2], A[2*i2+1]);
            *reinterpret_cast<ulonglong2*>(g1 + i2*1024) = make_ulonglong2(B[2*i2], B[2*i2+1]);
        }
    }
}

// ---- GEMM helpers ----
__device__ __forceinline__ void gemmL0(const ulonglong2* __restrict__ w,
                                       const float* __restrict__ base,
                                       const int* __restrict__ offA,
                                       const int* __restrict__ offB,
                                       u64* acc)
{
#pragma unroll
    for (int kk = 0; kk < 64; kk += 8) {
        ulonglong2 wv[4], hA[4], hB[4];
#pragma unroll
        for (int j = 0; j < 4; ++j) {
            const float* row = base + (kk + j) * 32;
            wv[j] = w[(kk + j) * 64];
            hA[j] = *reinterpret_cast<const ulonglong2*>(row + offA[j]);
            hB[j] = *reinterpret_cast<const ulonglong2*>(row + offB[j]);
        }
#pragma unroll
        for (int j = 0; j < 4; ++j) {
            acc[0] = ffma2(wv[j].x, hA[j].x, acc[0]); acc[1] = ffma2(wv[j].y, hA[j].x, acc[1]);
            acc[2] = ffma2(wv[j].x, hA[j].y, acc[2]); acc[3] = ffma2(wv[j].y, hA[j].y, acc[3]);
            acc[4] = ffma2(wv[j].x, hB[j].x, acc[4]); acc[5] = ffma2(wv[j].y, hB[j].x, acc[5]);
            acc[6] = ffma2(wv[j].x, hB[j].y, acc[6]); acc[7] = ffma2(wv[j].y, hB[j].y, acc[7]);
        }
#pragma unroll
        for (int j = 0; j < 4; ++j) {
            const float* row = base + (kk + 4 + j) * 32;
            wv[j] = w[(kk + 4 + j) * 64];
            hA[j] = *reinterpret_cast<const ulonglong2*>(row + offA[4 + j]);
            hB[j] = *reinterpret_cast<const ulonglong2*>(row + offB[4 + j]);
        }
#pragma unroll
        for (int j = 0; j < 4; ++j) {
            acc[0] = ffma2(wv[j].x, hA[j].x, acc[0]); acc[1] = ffma2(wv[j].y, hA[j].x, acc[1]);
            acc[2] = ffma2(wv[j].x, hA[j].y, acc[2]); acc[3] = ffma2(wv[j].y, hA[j].y, acc[3]);
            acc[4] = ffma2(wv[j].x, hB[j].x, acc[4]); acc[5] = ffma2(wv[j].y, hB[j].x, acc[5]);
            acc[6] = ffma2(wv[j].x, hB[j].y, acc[6]); acc[7] = ffma2(wv[j].y, hB[j].y, acc[7]);
        }
    }
}

template<int N>
__device__ __forceinline__ void gemmL1(const ulonglong2* __restrict__ w,
                                       const float* __restrict__ base,
                                       const int* __restrict__ off,
                                       u64* acc)
{
#pragma unroll
    for (int kk = 0; kk < N; kk += 8) {
        ulonglong2 wv[4], hv[4];
#pragma unroll
        for (int j = 0; j < 4; ++j) {
            wv[j] = w[(kk + j) * 32];
            hv[j] = *reinterpret_cast<const ulonglong2*>(base + (kk + j) * 32 + off[j]);
        }
#pragma unroll
        for (int j = 0; j < 4; ++j) {
            acc[0] = ffma2(wv[j].x, hv[j].x, acc[0]); acc[1] = ffma2(wv[j].y, hv[j].x, acc[1]);
            acc[2] = ffma2(wv[j].x, hv[j].y, acc[2]); acc[3] = ffma2(wv[j].y, hv[j].y, acc[3]);
        }
#pragma unroll
        for (int j = 0; j < 4; ++j) {
            wv[j] = w[(kk + 4 + j) * 32];
            hv[j] = *reinterpret_cast<const ulonglong2*>(base + (kk + 4 + j) * 32 + off[4 + j]);
        }
#pragma unroll
        for (int j = 0; j < 4; ++j) {
            acc[0] = ffma2(wv[j].x, hv[j].x, acc[0]); acc[1] = ffma2(wv[j].y, hv[j].x, acc[1]);
            acc[2] = ffma2(wv[j].x, hv[j].y, acc[2]); acc[3] = ffma2(wv[j].y, hv[j].y, acc[3]);
        }
    }
}

template<int N>
__device__ __forceinline__ void gemmL2(const ulonglong2* __restrict__ w,
                                       const float* __restrict__ base,
                                       const int* __restrict__ off,
                                       u64& aif, u64& ago)
{
#pragma unroll
    for (int kk = 0; kk < N; kk += 8) {
        ulonglong2 wv[4]; u64 hv[4];
#pragma unroll
        for (int j = 0; j < 4; ++j) {
            wv[j] = w[(kk + j) * 16];
            hv[j] = *reinterpret_cast<const u64*>(base + (kk + j) * 32 + off[j]);
        }
#pragma unroll
        for (int j = 0; j < 4; ++j) {
            aif = ffma2(wv[j].x, hv[j], aif);
            ago = ffma2(wv[j].y, hv[j], ago);
        }
#pragma unroll
        for (int j = 0; j < 4; ++j) {
            wv[j] = w[(kk + 4 + j) * 16];
            hv[j] = *reinterpret_cast<const u64*>(base + (kk + 4 + j) * 32 + off[4 + j]);
        }
#pragma unroll
        for (int j = 0; j < 4; ++j) {
            aif = ffma2(wv[j].x, hv[j], aif);
            ago = ffma2(wv[j].y, hv[j], ago);
        }
    }
}

// ================== PHASE 2: layer-pipelined recurrent loop ==================
// Pipeline step s in [0,258): L0 computes h0(s), L1 computes h1(s-1), L2 computes h2(s-2).
// All reads use parity p=s&1 (published at previous sync); writes to p^1. ONE sync/step.
__global__ void __launch_bounds__(NT, 1) lstm3_rec_kernel(
    const float* __restrict__ U0,
    const float* __restrict__ W1, const float* __restrict__ U1, const float* __restrict__ b1,
    const float* __restrict__ W2, const float* __restrict__ U2, const float* __restrict__ b2,
    const float* __restrict__ Wd, const float* __restrict__ bd,
    float* __restrict__ out)
{
    extern __shared__ float sm[];
    const int tid = threadIdx.x;
    const int bx  = blockIdx.x;
    const int row0 = bx * ROWS;

    float* wp0 = sm + WP0_OFF;
    float* wp1 = sm + WP1_OFF;
    float* wp2 = sm + WP2_OFF;
    float* bp1 = sm + BP1_OFF;
    float* bp2 = sm + BP2_OFF;
    float* wds = sm + WDS_OFF;
    float* bds = sm + BDS_OFF;
    float* xzb = sm + XZB_OFF;
    float* h0g = sm + H0_OFF;
    float* h1g = sm + H1_OFF;
    float* h2g = sm + H2_OFF;

    // prefetch xz[t=0] into buffer 0
    {
        const float* gp = g_lstm_xz_scratch + ((size_t)bx * 256) * 4096 + tid*4;
        uint32_t sa = (uint32_t)__cvta_generic_to_shared(xzb + tid*4);
#pragma unroll
        for (int i2 = 0; i2 < 4; ++i2)
            cpasync16(sa + i2*1024*4, gp + i2*1024);
        asm volatile("cp.async.commit_group;" ::: "memory");
    }

    // ---- load + rearrange weights ----
    for (int idx = tid; idx < WP0_N; idx += NT) {
        int g = idx & 3, u = (idx >> 2) & 63, k = idx >> 8;
        wp0[idx] = U0[k*256 + g*64 + u];
    }
    for (int idx = tid; idx < WP1_N; idx += NT) {
        int g = idx & 3, u = (idx >> 2) & 31, k = idx >> 7;
        wp1[idx] = (k < 64) ? W1[k*128 + g*32 + u] : U1[(k-64)*128 + g*32 + u];
    }
    for (int idx = tid; idx < WP2_N; idx += NT) {
        int g = idx & 3, u = (idx >> 2) & 15, k = idx >> 6;
        wp2[idx] = (k < 32) ? W2[k*64 + g*16 + u] : U2[(k-32)*64 + g*16 + u];
    }
    if (tid < 128) bp1[tid] = b1[(tid & 3)*32 + (tid >> 2)];
    if (tid < 64)  bp2[tid] = b2[(tid & 3)*16 + (tid >> 2)];
    if (tid < 16)  wds[tid] = Wd[tid];
    if (tid == 0)  bds[0]   = bd[0];
    for (int idx = tid; idx < 2*2048 + 2*1024 + 2*512; idx += NT) h0g[idx] = 0.0f;
    asm volatile("cp.async.wait_group 0;" ::: "memory");
    __syncthreads();

    const int wrp = tid >> 5, lan = tid & 31;
    const int u0 = (wrp << 3) | (lan & 7), rg0 = lan >> 3;
    const int u1 = (wrp << 2) | (lan & 3), rg1 = lan >> 2;
    const int u2 = (wrp << 1) | (lan & 1), r2  = lan >> 1;

    int offA0[8], offB0[8], off1[8], off2[8];
#pragma unroll
    for (int j = 0; j < 8; ++j) {
        offA0[j] = 4 * ((2*rg0)     ^ j);
        offB0[j] = 4 * ((2*rg0 + 1) ^ j);
        off1[j]  = 4 * (rg1 ^ j);
        off2[j]  = 4 * ((r2 >> 1) ^ j) + 2 * (r2 & 1);
    }

    const ulonglong2 bias1 = reinterpret_cast<const ulonglong2*>(bp1)[u1];
    const ulonglong2 bias2 = reinterpret_cast<const ulonglong2*>(bp2)[u2];

    const ulonglong2* w0v = reinterpret_cast<const ulonglong2*>(wp0) + u0;
    const ulonglong2* w1v = reinterpret_cast<const ulonglong2*>(wp1) + u1;
    const ulonglong2* w2v = reinterpret_cast<const ulonglong2*>(wp2) + u2;

    float c0[4] = {0.f, 0.f, 0.f, 0.f};
    float c1[2] = {0.f, 0.f};
    float c2v   = 0.f;

    const uint32_t xz_sa = (uint32_t)__cvta_generic_to_shared(xzb + tid*4);

    for (int s = 0; s < TSEQ + 2; ++s) {
        const int p = s & 1;
        const float* h0r = h0g + p * 2048;  float* h0w = h0g + (p ^ 1) * 2048;
        const float* h1r = h1g + p * 1024;  float* h1w = h1g + (p ^ 1) * 1024;
        const float* h2r = h2g + p * 512;   float* h2w = h2g + (p ^ 1) * 512;
        const float* xzr = xzb + p * 4096;

        // prefetch xz[s+1]
        if (s + 1 < TSEQ) {
            const float* gp = g_lstm_xz_scratch + ((size_t)(bx*256 + s + 1)) * 4096 + tid*4;
            uint32_t sa = xz_sa + (p ^ 1) * 4096 * 4;
#pragma unroll
            for (int i2 = 0; i2 < 4; ++i2)
                cpasync16(sa + i2*1024*4, gp + i2*1024);
            asm volatile("cp.async.commit_group;" ::: "memory");
        }

        // ---- L0: h0(s) = f(xz(s), h0(s-1)) ----
        if (s < TSEQ) {
            u64 acc0[8];
#pragma unroll
            for (int i2 = 0; i2 < 4; ++i2) {
                ulonglong2 v = *reinterpret_cast<const ulonglong2*>(xzr + i2*1024 + tid*4);
                acc0[2*i2] = v.x; acc0[2*i2+1] = v.y;
            }
            gemmL0(w0v, h0r, offA0, offB0, acc0);
            float h0v[4];
#pragma unroll
            for (int r = 0; r < 4; ++r) {
                float2 zif = unpk(acc0[2*r]), zgo = unpk(acc0[2*r+1]);
                float ig = sigap(zif.x), fg = sigap(zif.y);
                float gg = tanhap(zgo.x), og = sigap(zgo.y);
                c0[r]  = fg * c0[r] + ig * gg;
                h0v[r] = og * tanhap(c0[r]);
            }
            float* hb = h0w + u0 * 32;
            const int sx = u0 & 7;
            *reinterpret_cast<float4*>(hb + 4*((2*rg0)     ^ sx)) = make_float4(h0v[0], h0v[0], h0v[1], h0v[1]);
            *reinterpret_cast<float4*>(hb + 4*((2*rg0 + 1) ^ sx)) = make_float4(h0v[2], h0v[2], h0v[3], h0v[3]);
        }

        // ---- L1: h1(s-1) = f(h0(s-1), h1(s-2)) ----
        if (s >= 1 && s < TSEQ + 1) {
            u64 acc1[4];
            acc1[0] = bias1.x; acc1[1] = bias1.y; acc1[2] = bias1.x; acc1[3] = bias1.y;
            gemmL1<64>(w1v,         h0r, off1, acc1);
            gemmL1<32>(w1v + 64*32, h1r, off1, acc1);
            float h1v[2];
#pragma unroll
            for (int r = 0; r < 2; ++r) {
                float2 zif = unpk(acc1[2*r]), zgo = unpk(acc1[2*r+1]);
                float ig = sigap(zif.x), fg = sigap(zif.y);
                float gg = tanhap(zgo.x), og = sigap(zgo.y);
                c1[r]  = fg * c1[r] + ig * gg;
                h1v[r] = og * tanhap(c1[r]);
            }
            *reinterpret_cast<float4*>(h1w + u1*32 + 4*(rg1 ^ (u1 & 7))) =
                make_float4(h1v[0], h1v[0], h1v[1], h1v[1]);
        }

        // ---- L2: h2(s-2) = f(h1(s-2), h2(s-3)) ----
        if (s >= 2) {
            u64 aif = bias2.x, ago = bias2.y;
            gemmL2<32>(w2v,         h1r, off2, aif, ago);
            gemmL2<16>(w2v + 32*16, h2r, off2, aif, ago);
            float2 zif = unpk(aif), zgo = unpk(ago);
            float ig = sigap(zif.x), fg = sigap(zif.y);
            float gg = tanhap(zgo.x), og = sigap(zgo.y);
            c2v = fg * c2v + ig * gg;
            float h2val = og * tanhap(c2v);
            *reinterpret_cast<u64*>(h2w + u2*32 + 4*((r2 >> 1) ^ (u2 & 7)) + 2*(r2 & 1)) = dup2(h2val);
        }

        asm volatile("cp.async.wait_group 0;" ::: "memory");
        __syncthreads();   // single publish point per step
    }

    // ---- Dense head: h2(255) computed at s=257 -> write parity (257&1)^1 = 0 ----
    if (tid < 16) {
        const float* h2f = h2g;   // buffer 0
        float s = bds[0];
#pragma unroll
        for (int j = 0; j < 16; ++j)
            s += h2f[j*32 + 4*((tid >> 1) ^ (j & 7)) + 2*(tid & 1)] * wds[j];
        out[row0 + tid] = s;
    }
}

extern "C" void kernel_launch(void* const* d_in, const int* in_sizes, int n_in,
                              void* d_out, int out_size)
{
    (void)in_sizes; (void)n_in; (void)out_size;
    const float* x  = (const float*)d_in[0];
    const float* W0 = (const float*)d_in[1];
    const float* U0 = (const float*)d_in[2];
    const float* b0 = (const float*)d_in[3];
    const float* W1 = (const float*)d_in[4];
    const float* U1 = (const float*)d_in[5];
    const float* b1 = (const float*)d_in[6];
    const float* W2 = (const float*)d_in[7];
    const float* U2 = (const float*)d_in[8];
    const float* b2 = (const float*)d_in[9];
    const float* Wd = (const float*)d_in[10];
    const float* bd = (const float*)d_in[11];
    float* out = (float*)d_out;

    cudaFuncSetAttribute(xz_kernel,
                         cudaFuncAttributeMaxDynamicSharedMemorySize, P1_BYTES);
    cudaFuncSetAttribute(lstm3_rec_kernel,
                         cudaFuncAttributeMaxDynamicSharedMemorySize, SMEM_BYTES);

    xz_kernel<<<dim3(NBLK, 8), NT, P1_BYTES>>>(x, W0, b0);
    lstm3_rec_kernel<<<NBLK, NT, SMEM_BYTES>>>(
        U0, W1, U1, b1, W2, U2, b2, Wd, bd, out);
}

// round 8
// speedup vs baseline: 1.3423x; 1.0018x over previous
#include <cuda_runtime.h>
#include <cstdint>

#define NT    256
#define ROWS  16
#define NBLK  128          // 2048/16
#define TSEQ  256
#define FIN   64

typedef unsigned long long u64;

// 512MB scratch: xz[bx][t][i2][tid][4 floats]  (per-thread accumulator layout)
__device__ float g_lstm_xz_scratch[134217728];

// ---------------- phase-2 smem layout (float offsets) ----------------
#define WP0_N   (64*64*4)             // U0 rearranged [k][u][g]
#define WP1_N   (96*32*4)
#define WP2_N   (48*16*4)
#define WP0_OFF 0
#define WP1_OFF 16384
#define WP2_OFF 28672
#define BP1_OFF 31744
#define BP2_OFF 31872
#define WDS_OFF 31936
#define BDS_OFF 31952
#define XZB_OFF 31968                 // double buffer 2x4096
#define H0_OFF  (XZB_OFF + 2*4096)    // h0 double [2][64*32]
#define H1_OFF  (H0_OFF + 2*2048)     // h1 double [2][32*32]
#define H2_OFF  (H1_OFF + 2*1024)     // h2 double [2][16*32]
#define SMEM_FLOATS (H2_OFF + 2*512)  // 47328
#define SMEM_BYTES  (SMEM_FLOATS*4)   // 189312

// ---------------- phase-1 smem layout ----------------
#define P1_WP   0
#define P1_BP   16384
#define P1_XS0  16640
#define P1_XS1  18688
#define P1_FLOATS 20736
#define P1_BYTES  (P1_FLOATS*4)

__device__ __forceinline__ u64 ffma2(u64 a, u64 b, u64 c) {
    u64 d; asm("fma.rn.f32x2 %0, %1, %2, %3;" : "=l"(d) : "l"(a), "l"(b), "l"(c));
    return d;
}
__device__ __forceinline__ u64 dup2(float x) {
    u64 d; asm("mov.b64 %0, {%1, %1};" : "=l"(d) : "f"(x));
    return d;
}
__device__ __forceinline__ float2 unpk(u64 v) {
    float2 r; asm("mov.b64 {%0, %1}, %2;" : "=f"(r.x), "=f"(r.y) : "l"(v));
    return r;
}
__device__ __forceinline__ float tanhap(float x) {
    float y; asm("tanh.approx.f32 %0, %1;" : "=f"(y) : "f"(x));
    return y;
}
__device__ __forceinline__ float sigap(float x) {
    return fmaf(0.5f, tanhap(0.5f * x), 0.5f);
}
__device__ __forceinline__ void cpasync16(uint32_t saddr, const float* g) {
    asm volatile("cp.async.ca.shared.global [%0], [%1], 16;" :: "r"(saddr), "l"(g));
}

// ================== PHASE 1: xz = x@W0 + b0 for all (b,t) ==================
__global__ void __launch_bounds__(NT, 2) xz_kernel(
    const float* __restrict__ x,
    const float* __restrict__ W0,
    const float* __restrict__ b0)
{
    extern __shared__ float sm[];
    float* wp  = sm + P1_WP;
    float* bp  = sm + P1_BP;
    float* xs0 = sm + P1_XS0;
    float* xs1 = sm + P1_XS1;
    const int tid = threadIdx.x;

    for (int idx = tid; idx < 64*64*4; idx += NT) {
        int g = idx & 3, u = (idx >> 2) & 63, k = idx >> 8;
        wp[idx] = W0[k*256 + g*64 + u];
    }
    if (tid < 256) bp[tid] = b0[(tid & 3)*64 + (tid >> 2)];
    __syncthreads();

    const int wrp = tid >> 5, lan = tid & 31;
    const int u0 = (wrp << 3) | (lan & 7), rg0 = lan >> 3;
    int offA[8], offB[8];
#pragma unroll
    for (int j = 0; j < 8; ++j) {
        offA[j] = 4 * ((2*rg0)     ^ j);
        offB[j] = 4 * ((2*rg0 + 1) ^ j);
    }
    const ulonglong2 bias = reinterpret_cast<const ulonglong2*>(bp)[u0];
    const ulonglong2* wv  = reinterpret_cast<const ulonglong2*>(wp) + u0;

    const int f0 = tid & 63;
    const int ra = tid >> 6;
    const int row0  = blockIdx.x * ROWS;
    const int tbase = blockIdx.y * 32;
    const size_t xrow = (size_t)(row0 + 4*ra) * (TSEQ*FIN) + f0;
    float* s0 = xs0 + f0*32;
    float* s1 = xs1 + f0*32;
    const int sl0 = 4*((2*ra)     ^ (f0 & 7));
    const int sl1 = 4*((2*ra + 1) ^ (f0 & 7));

    float xr[8];
#pragma unroll
    for (int j = 0; j < 4; ++j) {
        xr[j]   = x[xrow + (size_t)j*(TSEQ*FIN) + (size_t)tbase*FIN];
        xr[4+j] = x[xrow + (size_t)j*(TSEQ*FIN) + (size_t)(tbase+1)*FIN];
    }

    for (int tp = 0; tp < 16; ++tp) {
        const int t0 = tbase + 2*tp;
        __syncthreads();
        *reinterpret_cast<float4*>(s0 + sl0) = make_float4(xr[0], xr[0], xr[1], xr[1]);
        *reinterpret_cast<float4*>(s0 + sl1) = make_float4(xr[2], xr[2], xr[3], xr[3]);
        *reinterpret_cast<float4*>(s1 + sl0) = make_float4(xr[4], xr[4], xr[5], xr[5]);
        *reinterpret_cast<float4*>(s1 + sl1) = make_float4(xr[6], xr[6], xr[7], xr[7]);
        __syncthreads();

        if (tp < 15) {
#pragma unroll
            for (int j = 0; j < 4; ++j) {
                xr[j]   = x[xrow + (size_t)j*(TSEQ*FIN) + (size_t)(t0+2)*FIN];
                xr[4+j] = x[xrow + (size_t)j*(TSEQ*FIN) + (size_t)(t0+3)*FIN];
            }
        }

        u64 A[8], B[8];
#pragma unroll
        for (int r = 0; r < 4; ++r) {
            A[2*r] = bias.x; A[2*r+1] = bias.y;
            B[2*r] = bias.x; B[2*r+1] = bias.y;
        }
#pragma unroll 8
        for (int k = 0; k < 64; ++k) {
            const int j = k & 7;
            ulonglong2 w  = wv[k*64];
            ulonglong2 a0 = *reinterpret_cast<const ulonglong2*>(xs0 + k*32 + offA[j]);
            ulonglong2 b0v= *reinterpret_cast<const ulonglong2*>(xs0 + k*32 + offB[j]);
            ulonglong2 a1 = *reinterpret_cast<const ulonglong2*>(xs1 + k*32 + offA[j]);
            ulonglong2 b1v= *reinterpret_cast<const ulonglong2*>(xs1 + k*32 + offB[j]);
            A[0]=ffma2(w.x,a0.x,A[0]);  A[1]=ffma2(w.y,a0.x,A[1]);
            A[2]=ffma2(w.x,a0.y,A[2]);  A[3]=ffma2(w.y,a0.y,A[3]);
            A[4]=ffma2(w.x,b0v.x,A[4]); A[5]=ffma2(w.y,b0v.x,A[5]);
            A[6]=ffma2(w.x,b0v.y,A[6]); A[7]=ffma2(w.y,b0v.y,A[7]);
            B[0]=ffma2(w.x,a1.x,B[0]);  B[1]=ffma2(w.y,a1.x,B[1]);
            B[2]=ffma2(w.x,a1.y,B[2]);  B[3]=ffma2(w.y,a1.y,B[3]);
            B[4]=ffma2(w.x,b1v.x,B[4]); B[5]=ffma2(w.y,b1v.x,B[5]);
            B[6]=ffma2(w.x,b1v.y,B[6]); B[7]=ffma2(w.y,b1v.y,B[7]);
        }
        float* g0 = g_lstm_xz_scratch + ((size_t)(blockIdx.x*256 + t0)) * 4096 + tid*4;
        float* g1 = g0 + 4096;
#pragma unroll
        for (int i2 = 0; i2 < 4; ++i2) {
            *reinterpret_cast<ulonglong2*>(g0 + i2*1024) = make_ulonglong2(A[2*i2], A[2*i2+1]);
            *reinterpret_cast<ulonglong2*>(g1 + i2*1024) = make_ulonglong2(B[2*i2], B[2*i2+1]);
        }
    }
}

// ---- GEMM helpers ----
__device__ __forceinline__ void gemmL0(const ulonglong2* __restrict__ w,
                                       const float* __restrict__ base,
                                       const int* __restrict__ offA,
                                       const int* __restrict__ offB,
                                       u64* acc)
{
#pragma unroll
    for (int kk = 0; kk < 64; kk += 8) {
        ulonglong2 wv[4], hA[4], hB[4];
#pragma unroll
        for (int j = 0; j < 4; ++j) {
            const float* row = base + (kk + j) * 32;
            wv[j] = w[(kk + j) * 64];
            hA[j] = *reinterpret_cast<const ulonglong2*>(row + offA[j]);
            hB[j] = *reinterpret_cast<const ulonglong2*>(row + offB[j]);
        }
#pragma unroll
        for (int j = 0; j < 4; ++j) {
            acc[0] = ffma2(wv[j].x, hA[j].x, acc[0]); acc[1] = ffma2(wv[j].y, hA[j].x, acc[1]);
            acc[2] = ffma2(wv[j].x, hA[j].y, acc[2]); acc[3] = ffma2(wv[j].y, hA[j].y, acc[3]);
            acc[4] = ffma2(wv[j].x, hB[j].x, acc[4]); acc[5] = ffma2(wv[j].y, hB[j].x, acc[5]);
            acc[6] = ffma2(wv[j].x, hB[j].y, acc[6]); acc[7] = ffma2(wv[j].y, hB[j].y, acc[7]);
        }
#pragma unroll
        for (int j = 0; j < 4; ++j) {
            const float* row = base + (kk + 4 + j) * 32;
            wv[j] = w[(kk + 4 + j) * 64];
            hA[j] = *reinterpret_cast<const ulonglong2*>(row + offA[4 + j]);
            hB[j] = *reinterpret_cast<const ulonglong2*>(row + offB[4 + j]);
        }
#pragma unroll
        for (int j = 0; j < 4; ++j) {
            acc[0] = ffma2(wv[j].x, hA[j].x, acc[0]); acc[1] = ffma2(wv[j].y, hA[j].x, acc[1]);
            acc[2] = ffma2(wv[j].x, hA[j].y, acc[2]); acc[3] = ffma2(wv[j].y, hA[j].y, acc[3]);
            acc[4] = ffma2(wv[j].x, hB[j].x, acc[4]); acc[5] = ffma2(wv[j].y, hB[j].x, acc[5]);
            acc[6] = ffma2(wv[j].x, hB[j].y, acc[6]); acc[7] = ffma2(wv[j].y, hB[j].y, acc[7]);
        }
    }
}

template<int N>
__device__ __forceinline__ void gemmL1(const ulonglong2* __restrict__ w,
                                       const float* __restrict__ base,
                                       const int* __restrict__ off,
                                       u64* acc)
{
#pragma unroll
    for (int kk = 0; kk < N; kk += 8) {
        ulonglong2 wv[4], hv[4];
#pragma unroll
        for (int j = 0; j < 4; ++j) {
            wv[j] = w[(kk + j) * 32];
            hv[j] = *reinterpret_cast<const ulonglong2*>(base + (kk + j) * 32 + off[j]);
        }
#pragma unroll
        for (int j = 0; j < 4; ++j) {
            acc[0] = ffma2(wv[j].x, hv[j].x, acc[0]); acc[1] = ffma2(wv[j].y, hv[j].x, acc[1]);
            acc[2] = ffma2(wv[j].x, hv[j].y, acc[2]); acc[3] = ffma2(wv[j].y, hv[j].y, acc[3]);
        }
#pragma unroll
        for (int j = 0; j < 4; ++j) {
            wv[j] = w[(kk + 4 + j) * 32];
            hv[j] = *reinterpret_cast<const ulonglong2*>(base + (kk + 4 + j) * 32 + off[4 + j]);
        }
#pragma unroll
        for (int j = 0; j < 4; ++j) {
            acc[0] = ffma2(wv[j].x, hv[j].x, acc[0]); acc[1] = ffma2(wv[j].y, hv[j].x, acc[1]);
            acc[2] = ffma2(wv[j].x, hv[j].y, acc[2]); acc[3] = ffma2(wv[j].y, hv[j].y, acc[3]);
        }
    }
}

template<int N>
__device__ __forceinline__ void gemmL2(const ulonglong2* __restrict__ w,
                                       const float* __restrict__ base,
                                       const int* __restrict__ off,
                                       u64& aif, u64& ago)
{
#pragma unroll
    for (int kk = 0; kk < N; kk += 8) {
        ulonglong2 wv[4]; u64 hv[4];
#pragma unroll
        for (int j = 0; j < 4; ++j) {
            wv[j] = w[(kk + j) * 16];
            hv[j] = *reinterpret_cast<const u64*>(base + (kk + j) * 32 + off[j]);
        }
#pragma unroll
        for (int j = 0; j < 4; ++j) {
            aif = ffma2(wv[j].x, hv[j], aif);
            ago = ffma2(wv[j].y, hv[j], ago);
        }
#pragma unroll
        for (int j = 0; j < 4; ++j) {
            wv[j] = w[(kk + 4 + j) * 16];
            hv[j] = *reinterpret_cast<const u64*>(base + (kk + 4 + j) * 32 + off[4 + j]);
        }
#pragma unroll
        for (int j = 0; j < 4; ++j) {
            aif = ffma2(wv[j].x, hv[j], aif);
            ago = ffma2(wv[j].y, hv[j], ago);
        }
    }
}

// ================== PHASE 2: layer-pipelined recurrent loop ==================
// Pipeline step s in [0,258): L0 computes h0(s), L1 computes h1(s-1), L2 computes h2(s-2).
// All reads use parity p=s&1 (published at previous sync); writes to p^1. ONE sync/step.
__global__ void __launch_bounds__(NT, 1) lstm3_rec_kernel(
    const float* __restrict__ U0,
    const float* __restrict__ W1, const float* __restrict__ U1, const float* __restrict__ b1,
    const float* __restrict__ W2, const float* __restrict__ U2, const float* __restrict__ b2,
    const float* __restrict__ Wd, const float* __restrict__ bd,
    float* __restrict__ out)
{
    extern __shared__ float sm[];
    const int tid = threadIdx.x;
    const int bx  = blockIdx.x;
    const int row0 = bx * ROWS;

    float* wp0 = sm + WP0_OFF;
    float* wp1 = sm + WP1_OFF;
    float* wp2 = sm + WP2_OFF;
    float* bp1 = sm + BP1_OFF;
    float* bp2 = sm + BP2_OFF;
    float* wds = sm + WDS_OFF;
    float* bds = sm + BDS_OFF;
    float* xzb = sm + XZB_OFF;
    float* h0g = sm + H0_OFF;
    float* h1g = sm + H1_OFF;
    float* h2g = sm + H2_OFF;

    // prefetch xz[t=0] into buffer 0
    {
        const float* gp = g_lstm_xz_scratch + ((size_t)bx * 256) * 4096 + tid*4;
        uint32_t sa = (uint32_t)__cvta_generic_to_shared(xzb + tid*4);
#pragma unroll
        for (int i2 = 0; i2 < 4; ++i2)
            cpasync16(sa + i2*1024*4, gp + i2*1024);
        asm volatile("cp.async.commit_group;" ::: "memory");
    }

    // ---- load + rearrange weights ----
    for (int idx = tid; idx < WP0_N; idx += NT) {
        int g = idx & 3, u = (idx >> 2) & 63, k = idx >> 8;
        wp0[idx] = U0[k*256 + g*64 + u];
    }
    for (int idx = tid; idx < WP1_N; idx += NT) {
        int g = idx & 3, u = (idx >> 2) & 31, k = idx >> 7;
        wp1[idx] = (k < 64) ? W1[k*128 + g*32 + u] : U1[(k-64)*128 + g*32 + u];
    }
    for (int idx = tid; idx < WP2_N; idx += NT) {
        int g = idx & 3, u = (idx >> 2) & 15, k = idx >> 6;
        wp2[idx] = (k < 32) ? W2[k*64 + g*16 + u] : U2[(k-32)*64 + g*16 + u];
    }
    if (tid < 128) bp1[tid] = b1[(tid & 3)*32 + (tid >> 2)];
    if (tid < 64)  bp2[tid] = b2[(tid & 3)*16 + (tid >> 2)];
    if (tid < 16)  wds[tid] = Wd[tid];
    if (tid == 0)  bds[0]   = bd[0];
    for (int idx = tid; idx < 2*2048 + 2*1024 + 2*512; idx += NT) h0g[idx] = 0.0f;
    asm volatile("cp.async.wait_group 0;" ::: "memory");
    __syncthreads();

    const int wrp = tid >> 5, lan = tid & 31;
    const int u0 = (wrp << 3) | (lan & 7), rg0 = lan >> 3;
    const int u1 = (wrp << 2) | (lan & 3), rg1 = lan >> 2;
    const int u2 = (wrp << 1) | (lan & 1), r2  = lan >> 1;

    int offA0[8], offB0[8], off1[8], off2[8];
#pragma unroll
    for (int j = 0; j < 8; ++j) {
        offA0[j] = 4 * ((2*rg0)     ^ j);
        offB0[j] = 4 * ((2*rg0 + 1) ^ j);
        off1[j]  = 4 * (rg1 ^ j);
        off2[j]  = 4 * ((r2 >> 1) ^ j) + 2 * (r2 & 1);
    }

    const ulonglong2 bias1 = reinterpret_cast<const ulonglong2*>(bp1)[u1];
    const ulonglong2 bias2 = reinterpret_cast<const ulonglong2*>(bp2)[u2];

    const ulonglong2* w0v = reinterpret_cast<const ulonglong2*>(wp0) + u0;
    const ulonglong2* w1v = reinterpret_cast<const ulonglong2*>(wp1) + u1;
    const ulonglong2* w2v = reinterpret_cast<const ulonglong2*>(wp2) + u2;

    float c0[4] = {0.f, 0.f, 0.f, 0.f};
    float c1[2] = {0.f, 0.f};
    float c2v   = 0.f;

    const uint32_t xz_sa = (uint32_t)__cvta_generic_to_shared(xzb + tid*4);

    for (int s = 0; s < TSEQ + 2; ++s) {
        const int p = s & 1;
        const float* h0r = h0g + p * 2048;  float* h0w = h0g + (p ^ 1) * 2048;
        const float* h1r = h1g + p * 1024;  float* h1w = h1g + (p ^ 1) * 1024;
        const float* h2r = h2g + p * 512;   float* h2w = h2g + (p ^ 1) * 512;
        const float* xzr = xzb + p * 4096;

        // prefetch xz[s+1]
        if (s + 1 < TSEQ) {
            const float* gp = g_lstm_xz_scratch + ((size_t)(bx*256 + s + 1)) * 4096 + tid*4;
            uint32_t sa = xz_sa + (p ^ 1) * 4096 * 4;
#pragma unroll
            for (int i2 = 0; i2 < 4; ++i2)
                cpasync16(sa + i2*1024*4, gp + i2*1024);
            asm volatile("cp.async.commit_group;" ::: "memory");
        }

        // ---- L0: h0(s) = f(xz(s), h0(s-1)) ----
        if (s < TSEQ) {
            u64 acc0[8];
#pragma unroll
            for (int i2 = 0; i2 < 4; ++i2) {
                ulonglong2 v = *reinterpret_cast<const ulonglong2*>(xzr + i2*1024 + tid*4);
                acc0[2*i2] = v.x; acc0[2*i2+1] = v.y;
            }
            gemmL0(w0v, h0r, offA0, offB0, acc0);
            float h0v[4];
#pragma unroll
            for (int r = 0; r < 4; ++r) {
                float2 zif = unpk(acc0[2*r]), zgo = unpk(acc0[2*r+1]);
                float ig = sigap(zif.x), fg = sigap(zif.y);
                float gg = tanhap(zgo.x), og = sigap(zgo.y);
                c0[r]  = fg * c0[r] + ig * gg;
                h0v[r] = og * tanhap(c0[r]);
            }
            float* hb = h0w + u0 * 32;
            const int sx = u0 & 7;
            *reinterpret_cast<float4*>(hb + 4*((2*rg0)     ^ sx)) = make_float4(h0v[0], h0v[0], h0v[1], h0v[1]);
            *reinterpret_cast<float4*>(hb + 4*((2*rg0 + 1) ^ sx)) = make_float4(h0v[2], h0v[2], h0v[3], h0v[3]);
        }

        // ---- L1: h1(s-1) = f(h0(s-1), h1(s-2)) ----
        if (s >= 1 && s < TSEQ + 1) {
            u64 acc1[4];
            acc1[0] = bias1.x; acc1[1] = bias1.y; acc1[2] = bias1.x; acc1[3] = bias1.y;
            gemmL1<64>(w1v,         h0r, off1, acc1);
            gemmL1<32>(w1v + 64*32, h1r, off1, acc1);
            float h1v[2];
#pragma unroll
            for (int r = 0; r < 2; ++r) {
                float2 zif = unpk(acc1[2*r]), zgo = unpk(acc1[2*r+1]);
                float ig = sigap(zif.x), fg = sigap(zif.y);
                float gg = tanhap(zgo.x), og = sigap(zgo.y);
                c1[r]  = fg * c1[r] + ig * gg;
                h1v[r] = og * tanhap(c1[r]);
            }
            *reinterpret_cast<float4*>(h1w + u1*32 + 4*(rg1 ^ (u1 & 7))) =
                make_float4(h1v[0], h1v[0], h1v[1], h1v[1]);
        }

        // ---- L2: h2(s-2) = f(h1(s-2), h2(s-3)) ----
        if (s >= 2) {
            u64 aif = bias2.x, ago = bias2.y;
            gemmL2<32>(w2v,         h1r, off2, aif, ago);
            gemmL2<16>(w2v + 32*16, h2r, off2, aif, ago);
            float2 zif = unpk(aif), zgo = unpk(ago);
            float ig = sigap(zif.x), fg = sigap(zif.y);
            float gg = tanhap(zgo.x), og = sigap(zgo.y);
            c2v = fg * c2v + ig * gg;
            float h2val = og * tanhap(c2v);
            *reinterpret_cast<u64*>(h2w + u2*32 + 4*((r2 >> 1) ^ (u2 & 7)) + 2*(r2 & 1)) = dup2(h2val);
        }

        asm volatile("cp.async.wait_group 0;" ::: "memory");
        __syncthreads();   // single publish point per step
    }

    // ---- Dense head: h2(255) computed at s=257 -> write parity (257&1)^1 = 0 ----
    if (tid < 16) {
        const float* h2f = h2g;   // buffer 0
        float s = bds[0];
#pragma unroll
        for (int j = 0; j < 16; ++j)
            s += h2f[j*32 + 4*((tid >> 1) ^ (j & 7)) + 2*(tid & 1)] * wds[j];
        out[row0 + tid] = s;
    }
}

extern "C" void kernel_launch(void* const* d_in, const int* in_sizes, int n_in,
                              void* d_out, int out_size)
{
    (void)in_sizes; (void)n_in; (void)out_size;
    const float* x  = (const float*)d_in[0];
    const float* W0 = (const float*)d_in[1];
    const float* U0 = (const float*)d_in[2];
    const float* b0 = (const float*)d_in[3];
    const float* W1 = (const float*)d_in[4];
    const float* U1 = (const float*)d_in[5];
    const float* b1 = (const float*)d_in[6];
    const float* W2 = (const float*)d_in[7];
    const float* U2 = (const float*)d_in[8];
    const float* b2 = (const float*)d_in[9];
    const float* Wd = (const float*)d_in[10];
    const float* bd = (const float*)d_in[11];
    float* out = (float*)d_out;

    cudaFuncSetAttribute(xz_kernel,
                         cudaFuncAttributeMaxDynamicSharedMemorySize, P1_BYTES);
    cudaFuncSetAttribute(lstm3_rec_kernel,
                         cudaFuncAttributeMaxDynamicSharedMemorySize, SMEM_BYTES);

    xz_kernel<<<dim3(NBLK, 8), NT, P1_BYTES>>>(x, W0, b0);
    lstm3_rec_kernel<<<NBLK, NT, SMEM_BYTES>>>(
        U0, W1, U1, b1, W2, U2, b2, Wd, bd, out);
}

// round 10
// speedup vs baseline: 2.2947x; 1.7095x over previous
#include <cuda_runtime.h>
#include <cuda_bf16.h>
#include <mma.h>
#include <cstdint>
using namespace nvcuda;

#define NT    256
#define ROWS  16
#define NBLK  128
#define TSEQ  256
#define FIN   64
typedef unsigned long long u64;

// xz scratch: [bx][t][m(256)][row(16)] fp32
__device__ float g_xz[134217728];
// weight matrices, bf16 hi/lo, row-major [m][k] with padded ld
__device__ __nv_bfloat16 g_A0h[256*72], g_A0l[256*72];   // U0^T  m=256, k=64, ld=72
__device__ __nv_bfloat16 g_A1Wh[128*72], g_A1Wl[128*72]; // W1^T  m=128, k=64, ld=72
__device__ __nv_bfloat16 g_A1Uh[128*40], g_A1Ul[128*40]; // U1^T  m=128, k=32, ld=40
__device__ __nv_bfloat16 g_A2Wh[64*40],  g_A2Wl[64*40];  // W2^T  m=64,  k=32, ld=40
__device__ __nv_bfloat16 g_A2Uh[64*24],  g_A2Ul[64*24];  // U2^T  m=64,  k=16, ld=24

// ---------------- phase-1 smem (floats) ----------------
#define P1_WP   0
#define P1_BP   16384
#define P1_XS0  16640
#define P1_XS1  18688
#define P1_FLOATS 20736
#define P1_BYTES  (P1_FLOATS*4)

// ---------------- rec smem (bytes) ----------------
#define XZO  0          // 2 x 16384
#define BTO  32768      // 2 x 8704 (bf16: h0hi 1152el, h0lo, h1hi 640, h1lo, h2hi 384, h2lo)
#define Z0O  50176      // 256 x 24 f32
#define Z1O  74752      // 128 x 24
#define Z2O  87040      // 64 x 24
#define HFO  93184      // 16 x 16 f32
#define SMEM2 94208

__device__ __forceinline__ uint32_t smem_u32(const void* p) {
    uint32_t a;
    asm("{ .reg .u64 t; cvta.to.shared.u64 t, %1; cvt.u32.u64 %0, t; }" : "=r"(a) : "l"(p));
    return a;
}
__device__ __forceinline__ void cpasync16(uint32_t saddr, const float* g) {
    asm volatile("cp.async.ca.shared.global [%0], [%1], 16;" :: "r"(saddr), "l"(g));
}
__device__ __forceinline__ u64 ffma2(u64 a, u64 b, u64 c) {
    u64 d; asm("fma.rn.f32x2 %0, %1, %2, %3;" : "=l"(d) : "l"(a), "l"(b), "l"(c));
    return d;
}
__device__ __forceinline__ float2 unpk(u64 v) {
    float2 r; asm("mov.b64 {%0, %1}, %2;" : "=f"(r.x), "=f"(r.y) : "l"(v));
    return r;
}
__device__ __forceinline__ float tanhap(float x) {
    float y; asm("tanh.approx.f32 %0, %1;" : "=f"(y) : "f"(x));
    return y;
}
__device__ __forceinline__ float sigap(float x) { return fmaf(0.5f, tanhap(0.5f*x), 0.5f); }

// ========== PROLOGUE: split weights into bf16 hi/lo, [m][k] row-major ==========
__global__ void wconv_kernel(const float* __restrict__ U0,
                             const float* __restrict__ W1, const float* __restrict__ U1,
                             const float* __restrict__ W2, const float* __restrict__ U2)
{
    const int t = blockIdx.x * blockDim.x + threadIdx.x;
    const int S = gridDim.x * blockDim.x;
    for (int i = t; i < 256*72; i += S) {
        int m = i / 72, k = i % 72;
        float v = (k < 64) ? U0[k*256 + m] : 0.f;
        __nv_bfloat16 h = __float2bfloat16(v);
        g_A0h[i] = h; g_A0l[i] = __float2bfloat16(v - __bfloat162float(h));
    }
    for (int i = t; i < 128*72; i += S) {
        int m = i / 72, k = i % 72;
        float v = (k < 64) ? W1[k*128 + m] : 0.f;
        __nv_bfloat16 h = __float2bfloat16(v);
        g_A1Wh[i] = h; g_A1Wl[i] = __float2bfloat16(v - __bfloat162float(h));
    }
    for (int i = t; i < 128*40; i += S) {
        int m = i / 40, k = i % 40;
        float v = (k < 32) ? U1[k*128 + m] : 0.f;
        __nv_bfloat16 h = __float2bfloat16(v);
        g_A1Uh[i] = h; g_A1Ul[i] = __float2bfloat16(v - __bfloat162float(h));
    }
    for (int i = t; i < 64*40; i += S) {
        int m = i / 40, k = i % 40;
        float v = (k < 32) ? W2[k*64 + m] : 0.f;
        __nv_bfloat16 h = __float2bfloat16(v);
        g_A2Wh[i] = h; g_A2Wl[i] = __float2bfloat16(v - __bfloat162float(h));
    }
    for (int i = t; i < 64*24; i += S) {
        int m = i / 24, k = i % 24;
        float v = (k < 16) ? U2[k*64 + m] : 0.f;
        __nv_bfloat16 h = __float2bfloat16(v);
        g_A2Uh[i] = h; g_A2Ul[i] = __float2bfloat16(v - __bfloat162float(h));
    }
}

// ========== PHASE 1: xz = x@W0 + b0 (SIMT fp32, unchanged) ==========
__global__ void __launch_bounds__(NT, 2) xz_kernel(
    const float* __restrict__ x, const float* __restrict__ W0, const float* __restrict__ b0)
{
    extern __shared__ float sm[];
    float* wp  = sm + P1_WP;
    float* bp  = sm + P1_BP;
    float* xs0 = sm + P1_XS0;
    float* xs1 = sm + P1_XS1;
    const int tid = threadIdx.x;

    for (int idx = tid; idx < 64*64*4; idx += NT) {
        int g = idx & 3, u = (idx >> 2) & 63, k = idx >> 8;
        wp[idx] = W0[k*256 + g*64 + u];
    }
    if (tid < 256) bp[tid] = b0[(tid & 3)*64 + (tid >> 2)];
    __syncthreads();

    const int wrp = tid >> 5, lan = tid & 31;
    const int u0 = (wrp << 3) | (lan & 7), rg0 = lan >> 3;
    int offA[8], offB[8];
#pragma unroll
    for (int j = 0; j < 8; ++j) { offA[j] = 4*((2*rg0)^j); offB[j] = 4*((2*rg0+1)^j); }
    const ulonglong2 bias = reinterpret_cast<const ulonglong2*>(bp)[u0];
    const ulonglong2* wv  = reinterpret_cast<const ulonglong2*>(wp) + u0;

    const int f0 = tid & 63, ra = tid >> 6;
    const int row0 = blockIdx.x * ROWS, tbase = blockIdx.y * 32;
    const size_t xrow = (size_t)(row0 + 4*ra) * (TSEQ*FIN) + f0;
    float* s0 = xs0 + f0*32;
    float* s1 = xs1 + f0*32;
    const int sl0 = 4*((2*ra) ^ (f0 & 7)), sl1 = 4*((2*ra+1) ^ (f0 & 7));

    float xr[8];
#pragma unroll
    for (int j = 0; j < 4; ++j) {
        xr[j]   = x[xrow + (size_t)j*(TSEQ*FIN) + (size_t)tbase*FIN];
        xr[4+j] = x[xrow + (size_t)j*(TSEQ*FIN) + (size_t)(tbase+1)*FIN];
    }

    for (int tp = 0; tp < 16; ++tp) {
        const int t0 = tbase + 2*tp;
        __syncthreads();
        *reinterpret_cast<float4*>(s0 + sl0) = make_float4(xr[0], xr[0], xr[1], xr[1]);
        *reinterpret_cast<float4*>(s0 + sl1) = make_float4(xr[2], xr[2], xr[3], xr[3]);
        *reinterpret_cast<float4*>(s1 + sl0) = make_float4(xr[4], xr[4], xr[5], xr[5]);
        *reinterpret_cast<float4*>(s1 + sl1) = make_float4(xr[6], xr[6], xr[7], xr[7]);
        __syncthreads();

        if (tp < 15) {
#pragma unroll
            for (int j = 0; j < 4; ++j) {
                xr[j]   = x[xrow + (size_t)j*(TSEQ*FIN) + (size_t)(t0+2)*FIN];
                xr[4+j] = x[xrow + (size_t)j*(TSEQ*FIN) + (size_t)(t0+3)*FIN];
            }
        }

        u64 A[8], B[8];
#pragma unroll
        for (int r = 0; r < 4; ++r) { A[2*r]=bias.x; A[2*r+1]=bias.y; B[2*r]=bias.x; B[2*r+1]=bias.y; }
#pragma unroll 8
        for (int k = 0; k < 64; ++k) {
            const int j = k & 7;
            ulonglong2 w  = wv[k*64];
            ulonglong2 a0 = *reinterpret_cast<const ulonglong2*>(xs0 + k*32 + offA[j]);
            ulonglong2 b0v= *reinterpret_cast<const ulonglong2*>(xs0 + k*32 + offB[j]);
            ulonglong2 a1 = *reinterpret_cast<const ulonglong2*>(xs1 + k*32 + offA[j]);
            ulonglong2 b1v= *reinterpret_cast<const ulonglong2*>(xs1 + k*32 + offB[j]);
            A[0]=ffma2(w.x,a0.x,A[0]);  A[1]=ffma2(w.y,a0.x,A[1]);
            A[2]=ffma2(w.x,a0.y,A[2]);  A[3]=ffma2(w.y,a0.y,A[3]);
            A[4]=ffma2(w.x,b0v.x,A[4]); A[5]=ffma2(w.y,b0v.x,A[5]);
            A[6]=ffma2(w.x,b0v.y,A[6]); A[7]=ffma2(w.y,b0v.y,A[7]);
            B[0]=ffma2(w.x,a1.x,B[0]);  B[1]=ffma2(w.y,a1.x,B[1]);
            B[2]=ffma2(w.x,a1.y,B[2]);  B[3]=ffma2(w.y,a1.y,B[3]);
            B[4]=ffma2(w.x,b1v.x,B[4]); B[5]=ffma2(w.y,b1v.x,B[5]);
            B[6]=ffma2(w.x,b1v.y,B[6]); B[7]=ffma2(w.y,b1v.y,B[7]);
        }
        // scratch[t][m=g*64+u][row]
        float* gp = g_xz + (size_t)(blockIdx.x*256 + t0) * 4096;
#pragma unroll
        for (int half = 0; half < 2; ++half) {
            const u64* Ac = half ? B : A;
            float* gq = gp + half*4096 + u0*16 + 4*rg0;
            float2 r0if=unpk(Ac[0]), r0go=unpk(Ac[1]), r1if=unpk(Ac[2]), r1go=unpk(Ac[3]);
            float2 r2if=unpk(Ac[4]), r2go=unpk(Ac[5]), r3if=unpk(Ac[6]), r3go=unpk(Ac[7]);
            *reinterpret_cast<float4*>(gq)        = make_float4(r0if.x,r1if.x,r2if.x,r3if.x);
            *reinterpret_cast<float4*>(gq + 1024) = make_float4(r0if.y,r1if.y,r2if.y,r3if.y);
            *reinterpret_cast<float4*>(gq + 2048) = make_float4(r0go.x,r1go.x,r2go.x,r3go.x);
            *reinterpret_cast<float4*>(gq + 3072) = make_float4(r0go.y,r1go.y,r2go.y,r3go.y);
        }
    }
}

// ========== PHASE 2: wmma (HMMA) recurrent loop ==========
typedef wmma::fragment<wmma::matrix_a, 16,16,16, __nv_bfloat16, wmma::row_major> FragA;
typedef wmma::fragment<wmma::matrix_b, 16,16,16, __nv_bfloat16, wmma::col_major> FragB;
typedef wmma::fragment<wmma::accumulator, 16,16,16, float> FragC;

__global__ void __launch_bounds__(NT, 1) lstm3_rec_wmma(
    const float* __restrict__ b1, const float* __restrict__ b2,
    const float* __restrict__ Wd, const float* __restrict__ bd,
    float* __restrict__ out)
{
    extern __shared__ char smc[];
    const int tid = threadIdx.x, wid = tid >> 5, bx = blockIdx.x;
    const int lw = wid - 4;

    // zero both B parities
    for (int i = tid; i < 4352; i += NT) reinterpret_cast<uint32_t*>(smc + BTO)[i] = 0u;

    // prefetch xz(0) into buf 0
    {
        const float* gp = g_xz + (size_t)bx*256*4096 + tid*4;
        uint32_t sa = smem_u32(smc + XZO) + tid*16;
#pragma unroll
        for (int i2 = 0; i2 < 4; ++i2) cpasync16(sa + i2*4096, gp + i2*1024);
        asm volatile("cp.async.commit_group;" ::: "memory");
    }

    // resident A-hi fragments
    FragA ah[16];
    if (wid < 4) {
#pragma unroll
        for (int i = 0; i < 4; ++i)
#pragma unroll
            for (int kk = 0; kk < 4; ++kk)
                wmma::load_matrix_sync(ah[i*4+kk], g_A0h + (wid*4+i)*16*72 + kk*16, 72);
    } else {
#pragma unroll
        for (int t2 = 0; t2 < 2; ++t2) {
            const int mt = lw*2 + t2;
#pragma unroll
            for (int kk = 0; kk < 4; ++kk)
                wmma::load_matrix_sync(ah[t2*6+kk], g_A1Wh + mt*16*72 + kk*16, 72);
#pragma unroll
            for (int u = 0; u < 2; ++u)
                wmma::load_matrix_sync(ah[t2*6+4+u], g_A1Uh + mt*16*40 + u*16, 40);
        }
#pragma unroll
        for (int kk = 0; kk < 2; ++kk)
            wmma::load_matrix_sync(ah[12+kk], g_A2Wh + lw*16*40 + kk*16, 40);
        wmma::load_matrix_sync(ah[14], g_A2Uh + lw*16*24, 24);
    }

    // epilogue roles
    const int u0e = tid & 63,  q0 = tid >> 6;
    const int u1e = tid & 31,  q1 = (tid & 127) >> 5;
    const int u2e = tid & 15,  q2 = (tid & 63) >> 4;
    float b1r[4] = {0,0,0,0}, b2r[4] = {0,0,0,0};
    if (tid < 128) { b1r[0]=b1[u1e]; b1r[1]=b1[32+u1e]; b1r[2]=b1[64+u1e]; b1r[3]=b1[96+u1e]; }
    if (tid < 64)  { b2r[0]=b2[u2e]; b2r[1]=b2[16+u2e]; b2r[2]=b2[32+u2e]; b2r[3]=b2[48+u2e]; }
    float c0[4] = {0,0,0,0}, c1[4] = {0,0,0,0}, c2[4] = {0,0,0,0};

    float* z0 = reinterpret_cast<float*>(smc + Z0O);
    float* z1 = reinterpret_cast<float*>(smc + Z1O);
    float* z2 = reinterpret_cast<float*>(smc + Z2O);
    float* hf = reinterpret_cast<float*>(smc + HFO);

    asm volatile("cp.async.wait_group 0;" ::: "memory");
    __syncthreads();

    for (int s = 0; s < TSEQ + 2; ++s) {
        const int p = s & 1;

        // prefetch xz(s+1)
        if (s + 1 < TSEQ) {
            const float* gp = g_xz + (size_t)(bx*256 + s + 1)*4096 + tid*4;
            uint32_t sa = smem_u32(smc + XZO) + (p^1)*16384 + tid*16;
#pragma unroll
            for (int i2 = 0; i2 < 4; ++i2) cpasync16(sa + i2*4096, gp + i2*1024);
            asm volatile("cp.async.commit_group;" ::: "memory");
        }

        const __nv_bfloat16* br0h = reinterpret_cast<const __nv_bfloat16*>(smc + BTO + p*8704);
        const __nv_bfloat16* br0l = br0h + 1152;
        const __nv_bfloat16* br1h = br0h + 2304;
        const __nv_bfloat16* br1l = br0h + 2944;
        const __nv_bfloat16* br2h = br0h + 3584;
        const __nv_bfloat16* br2l = br0h + 3968;
        const float* xzp = reinterpret_cast<const float*>(smc + XZO + p*16384);

        FragB bh, bl;
        FragA al;
        FragC acc[4];

        if (wid < 4) {
            if (s < TSEQ) {
#pragma unroll
                for (int i = 0; i < 4; ++i)
                    wmma::load_matrix_sync(acc[i], xzp + (wid*4+i)*256, 16, wmma::mem_row_major);
#pragma unroll
                for (int kk = 0; kk < 4; ++kk) {
                    wmma::load_matrix_sync(bh, br0h + kk*16, 72);
                    wmma::load_matrix_sync(bl, br0l + kk*16, 72);
#pragma unroll
                    for (int i = 0; i < 4; ++i) {
                        wmma::mma_sync(acc[i], ah[i*4+kk], bh, acc[i]);
                        wmma::mma_sync(acc[i], ah[i*4+kk], bl, acc[i]);
                        wmma::load_matrix_sync(al, g_A0l + (wid*4+i)*16*72 + kk*16, 72);
                        wmma::mma_sync(acc[i], al, bh, acc[i]);
                    }
                }
#pragma unroll
                for (int i = 0; i < 4; ++i)
                    wmma::store_matrix_sync(z0 + (wid*4+i)*16*24, acc[i], 24, wmma::mem_row_major);
            }
        } else {
            if (s >= 1 && s <= TSEQ) {
                wmma::fill_fragment(acc[0], 0.0f);
                wmma::fill_fragment(acc[1], 0.0f);
#pragma unroll
                for (int kk = 0; kk < 4; ++kk) {
                    wmma::load_matrix_sync(bh, br0h + kk*16, 72);
                    wmma::load_matrix_sync(bl, br0l + kk*16, 72);
#pragma unroll
                    for (int t2 = 0; t2 < 2; ++t2) {
                        wmma::mma_sync(acc[t2], ah[t2*6+kk], bh, acc[t2]);
                        wmma::mma_sync(acc[t2], ah[t2*6+kk], bl, acc[t2]);
                        wmma::load_matrix_sync(al, g_A1Wl + (lw*2+t2)*16*72 + kk*16, 72);
                        wmma::mma_sync(acc[t2], al, bh, acc[t2]);
                    }
                }
#pragma unroll
                for (int u = 0; u < 2; ++u) {
                    wmma::load_matrix_sync(bh, br1h + u*16, 40);
                    wmma::load_matrix_sync(bl, br1l + u*16, 40);
#pragma unroll
                    for (int t2 = 0; t2 < 2; ++t2) {
                        wmma::mma_sync(acc[t2], ah[t2*6+4+u], bh, acc[t2]);
                        wmma::mma_sync(acc[t2], ah[t2*6+4+u], bl, acc[t2]);
                        wmma::load_matrix_sync(al, g_A1Ul + (lw*2+t2)*16*40 + u*16, 40);
                        wmma::mma_sync(acc[t2], al, bh, acc[t2]);
                    }
                }
#pragma unroll
                for (int t2 = 0; t2 < 2; ++t2)
                    wmma::store_matrix_sync(z1 + (lw*2+t2)*16*24, acc[t2], 24, wmma::mem_row_major);
            }
            if (s >= 2) {
                wmma::fill_fragment(acc[2], 0.0f);
#pragma unroll
                for (int kk = 0; kk < 2; ++kk) {
                    wmma::load_matrix_sync(bh, br1h + kk*16, 40);
                    wmma::load_matrix_sync(bl, br1l + kk*16, 40);
                    wmma::mma_sync(acc[2], ah[12+kk], bh, acc[2]);
                    wmma::mma_sync(acc[2], ah[12+kk], bl, acc[2]);
                    wmma::load_matrix_sync(al, g_A2Wl + lw*16*40 + kk*16, 40);
                    wmma::mma_sync(acc[2], al, bh, acc[2]);
                }
                wmma::load_matrix_sync(bh, br2h, 24);
                wmma::load_matrix_sync(bl, br2l, 24);
                wmma::mma_sync(acc[2], ah[14], bh, acc[2]);
                wmma::mma_sync(acc[2], ah[14], bl, acc[2]);
                wmma::load_matrix_sync(al, g_A2Ul + lw*16*24, 24);
                wmma::mma_sync(acc[2], al, bh, acc[2]);
                wmma::store_matrix_sync(z2 + lw*16*24, acc[2], 24, wmma::mem_row_major);
            }
        }
        __syncthreads();   // z published; B(p) reads complete

        __nv_bfloat16* bw0h = reinterpret_cast<__nv_bfloat16*>(smc + BTO + (p^1)*8704);
        __nv_bfloat16* bw0l = bw0h + 1152;
        __nv_bfloat16* bw1h = bw0h + 2304;
        __nv_bfloat16* bw1l = bw0h + 2944;
        __nv_bfloat16* bw2h = bw0h + 3584;
        __nv_bfloat16* bw2l = bw0h + 3968;

        if (s < TSEQ) {   // L0 epilogue: all threads
            float4 zi = *reinterpret_cast<const float4*>(z0 + (u0e      )*24 + 4*q0);
            float4 zf = *reinterpret_cast<const float4*>(z0 + (64 + u0e )*24 + 4*q0);
            float4 zg = *reinterpret_cast<const float4*>(z0 + (128 + u0e)*24 + 4*q0);
            float4 zo = *reinterpret_cast<const float4*>(z0 + (192 + u0e)*24 + 4*q0);
            float iv[4] = {zi.x,zi.y,zi.z,zi.w}, fv[4] = {zf.x,zf.y,zf.z,zf.w};
            float gv[4] = {zg.x,zg.y,zg.z,zg.w}, ov[4] = {zo.x,zo.y,zo.z,zo.w};
#pragma unroll
            for (int j = 0; j < 4; ++j) {
                float ig = sigap(iv[j]), fg = sigap(fv[j]);
                float gg = tanhap(gv[j]), og = sigap(ov[j]);
                c0[j] = fg * c0[j] + ig * gg;
                float h = og * tanhap(c0[j]);
                int n = 4*q0 + j;
                __nv_bfloat16 hi = __float2bfloat16(h);
                bw0h[n*72 + u0e] = hi;
                bw0l[n*72 + u0e] = __float2bfloat16(h - __bfloat162float(hi));
            }
        }
        if (s >= 1 && s <= TSEQ && tid < 128) {   // L1 epilogue
            float4 zi = *reinterpret_cast<const float4*>(z1 + (u1e     )*24 + 4*q1);
            float4 zf = *reinterpret_cast<const float4*>(z1 + (32 + u1e)*24 + 4*q1);
            float4 zg = *reinterpret_cast<const float4*>(z1 + (64 + u1e)*24 + 4*q1);
            float4 zo = *reinterpret_cast<const float4*>(z1 + (96 + u1e)*24 + 4*q1);
            float iv[4] = {zi.x,zi.y,zi.z,zi.w}, fv[4] = {zf.x,zf.y,zf.z,zf.w};
            float gv[4] = {zg.x,zg.y,zg.z,zg.w}, ov[4] = {zo.x,zo.y,zo.z,zo.w};
#pragma unroll
            for (int j = 0; j < 4; ++j) {
                float ig = sigap(iv[j] + b1r[0]), fg = sigap(fv[j] + b1r[1]);
                float gg = tanhap(gv[j] + b1r[2]), og = sigap(ov[j] + b1r[3]);
                c1[j] = fg * c1[j] + ig * gg;
                float h = og * tanhap(c1[j]);
                int n = 4*q1 + j;
                __nv_bfloat16 hi = __float2bfloat16(h);
                bw1h[n*40 + u1e] = hi;
                bw1l[n*40 + u1e] = __float2bfloat16(h - __bfloat162float(hi));
            }
        }
        if (s >= 2 && tid < 64) {   // L2 epilogue
            float4 zi = *reinterpret_cast<const float4*>(z2 + (u2e     )*24 + 4*q2);
            float4 zf = *reinterpret_cast<const float4*>(z2 + (16 + u2e)*24 + 4*q2);
            float4 zg = *reinterpret_cast<const float4*>(z2 + (32 + u2e)*24 + 4*q2);
            float4 zo = *reinterpret_cast<const float4*>(z2 + (48 + u2e)*24 + 4*q2);
            float iv[4] = {zi.x,zi.y,zi.z,zi.w}, fv[4] = {zf.x,zf.y,zf.z,zf.w};
            float gv[4] = {zg.x,zg.y,zg.z,zg.w}, ov[4] = {zo.x,zo.y,zo.z,zo.w};
#pragma unroll
            for (int j = 0; j < 4; ++j) {
                float ig = sigap(iv[j] + b2r[0]), fg = sigap(fv[j] + b2r[1]);
                float gg = tanhap(gv[j] + b2r[2]), og = sigap(ov[j] + b2r[3]);
                c2[j] = fg * c2[j] + ig * gg;
                float h = og * tanhap(c2[j]);
                int n = 4*q2 + j;
                __nv_bfloat16 hi = __float2bfloat16(h);
                bw2h[n*24 + u2e] = hi;
                bw2l[n*24 + u2e] = __float2bfloat16(h - __bfloat162float(hi));
                if (s == TSEQ + 1) hf[n*16 + u2e] = h;
            }
        }
        asm volatile("cp.async.wait_group 0;" ::: "memory");
        __syncthreads();   // h(p^1) + xz(p^1) published
    }

    // ---- Dense head ----
    if (tid < 16) {
        float a = bd[0];
#pragma unroll
        for (int u = 0; u < 16; ++u) a += hf[tid*16 + u] * Wd[u];
        out[bx*ROWS + tid] = a;
    }
}

extern "C" void kernel_launch(void* const* d_in, const int* in_sizes, int n_in,
                              void* d_out, int out_size)
{
    (void)in_sizes; (void)n_in; (void)out_size;
    const float* x  = (const float*)d_in[0];
    const float* W0 = (const float*)d_in[1];
    const float* U0 = (const float*)d_in[2];
    const float* b0 = (const float*)d_in[3];
    const float* W1 = (const float*)d_in[4];
    const float* U1 = (const float*)d_in[5];
    const float* b1 = (const float*)d_in[6];
    const float* W2 = (const float*)d_in[7];
    const float* U2 = (const float*)d_in[8];
    const float* b2 = (const float*)d_in[9];
    const float* Wd = (const float*)d_in[10];
    const float* bd = (const float*)d_in[11];
    float* out = (float*)d_out;

    cudaFuncSetAttribute(xz_kernel, cudaFuncAttributeMaxDynamicSharedMemorySize, P1_BYTES);
    cudaFuncSetAttribute(lstm3_rec_wmma, cudaFuncAttributeMaxDynamicSharedMemorySize, SMEM2);

    wconv_kernel<<<32, 256>>>(U0, W1, U1, W2, U2);
    xz_kernel<<<dim3(NBLK, 8), NT, P1_BYTES>>>(x, W0, b0);
    lstm3_rec_wmma<<<NBLK, NT, SMEM2>>>(b1, b2, Wd, bd, out);
}

// round 11
// speedup vs baseline: 3.0476x; 1.3281x over previous
#include <cuda_runtime.h>
#include <cuda_bf16.h>
#include <mma.h>
#include <cstdint>
using namespace nvcuda;

#define NT    256
#define ROWS  16
#define NBLK  128
#define TSEQ  256
#define FIN   64
typedef unsigned long long u64;

// xz scratch: [bx][t][m(256)][row(16)] fp32
__device__ float g_xz[134217728];
// weights, bf16 hi/lo, row-major [m][k] padded ld
__device__ __nv_bfloat16 g_W0h[256*72], g_W0l[256*72];   // W0^T  m=256, k=64, ld=72
__device__ __nv_bfloat16 g_A0h[256*72], g_A0l[256*72];   // U0^T  m=256, k=64, ld=72
__device__ __nv_bfloat16 g_A1Wh[128*72], g_A1Wl[128*72]; // W1^T  m=128, k=64, ld=72
__device__ __nv_bfloat16 g_A1Uh[128*40], g_A1Ul[128*40]; // U1^T  m=128, k=32, ld=40
__device__ __nv_bfloat16 g_A2Wh[64*40],  g_A2Wl[64*40];  // W2^T  m=64,  k=32, ld=40
__device__ __nv_bfloat16 g_A2Uh[64*24],  g_A2Ul[64*24];  // U2^T  m=64,  k=16, ld=24

// ---------------- phase-1 smem (bytes) ----------------
#define X1_B0R  0          // b0 replicated [256 m][16] f32 = 16384
#define X1_XS   16384      // 2 parities x (hi 2304 + lo 2304) = 9216
#define X1_BYTES 25600

// ---------------- rec smem (bytes) ----------------
#define XZO  0          // 2 x 16384
#define BTO  32768      // 2 x 8704 bf16 (h0hi 1152el, h0lo, h1hi 640, h1lo, h2hi 384, h2lo)
#define Z0O  50176      // 256 x 24 f32
#define Z1O  74752      // 128 x 24
#define Z2O  87040      // 64 x 24
#define HFO  93184      // 16 x 16 f32
#define SMEM2 94208

__device__ __forceinline__ uint32_t smem_u32(const void* p) {
    uint32_t a;
    asm("{ .reg .u64 t; cvta.to.shared.u64 t, %1; cvt.u32.u64 %0, t; }" : "=r"(a) : "l"(p));
    return a;
}
__device__ __forceinline__ void cpasync16(uint32_t saddr, const float* g) {
    asm volatile("cp.async.ca.shared.global [%0], [%1], 16;" :: "r"(saddr), "l"(g));
}
__device__ __forceinline__ float tanhap(float x) {
    float y; asm("tanh.approx.f32 %0, %1;" : "=f"(y) : "f"(x));
    return y;
}
__device__ __forceinline__ float sigap(float x) { return fmaf(0.5f, tanhap(0.5f*x), 0.5f); }

// ========== PROLOGUE: split weights into bf16 hi/lo ==========
__global__ void wconv_kernel(const float* __restrict__ W0, const float* __restrict__ U0,
                             const float* __restrict__ W1, const float* __restrict__ U1,
                             const float* __restrict__ W2, const float* __restrict__ U2)
{
    const int t = blockIdx.x * blockDim.x + threadIdx.x;
    const int S = gridDim.x * blockDim.x;
    for (int i = t; i < 256*72; i += S) {
        int m = i / 72, k = i % 72;
        float v = (k < 64) ? W0[k*256 + m] : 0.f;
        __nv_bfloat16 h = __float2bfloat16(v);
        g_W0h[i] = h; g_W0l[i] = __float2bfloat16(v - __bfloat162float(h));
    }
    for (int i = t; i < 256*72; i += S) {
        int m = i / 72, k = i % 72;
        float v = (k < 64) ? U0[k*256 + m] : 0.f;
        __nv_bfloat16 h = __float2bfloat16(v);
        g_A0h[i] = h; g_A0l[i] = __float2bfloat16(v - __bfloat162float(h));
    }
    for (int i = t; i < 128*72; i += S) {
        int m = i / 72, k = i % 72;
        float v = (k < 64) ? W1[k*128 + m] : 0.f;
        __nv_bfloat16 h = __float2bfloat16(v);
        g_A1Wh[i] = h; g_A1Wl[i] = __float2bfloat16(v - __bfloat162float(h));
    }
    for (int i = t; i < 128*40; i += S) {
        int m = i / 40, k = i % 40;
        float v = (k < 32) ? U1[k*128 + m] : 0.f;
        __nv_bfloat16 h = __float2bfloat16(v);
        g_A1Uh[i] = h; g_A1Ul[i] = __float2bfloat16(v - __bfloat162float(h));
    }
    for (int i = t; i < 64*40; i += S) {
        int m = i / 40, k = i % 40;
        float v = (k < 32) ? W2[k*64 + m] : 0.f;
        __nv_bfloat16 h = __float2bfloat16(v);
        g_A2Wh[i] = h; g_A2Wl[i] = __float2bfloat16(v - __bfloat162float(h));
    }
    for (int i = t; i < 64*24; i += S) {
        int m = i / 24, k = i % 24;
        float v = (k < 16) ? U2[k*64 + m] : 0.f;
        __nv_bfloat16 h = __float2bfloat16(v);
        g_A2Uh[i] = h; g_A2Ul[i] = __float2bfloat16(v - __bfloat162float(h));
    }
}

typedef wmma::fragment<wmma::matrix_a, 16,16,16, __nv_bfloat16, wmma::row_major> FragA;
typedef wmma::fragment<wmma::matrix_b, 16,16,16, __nv_bfloat16, wmma::col_major> FragB;
typedef wmma::fragment<wmma::accumulator, 16,16,16, float> FragC;

// ========== PHASE 1: xz = x@W0 + b0 via wmma (bf16x3) ==========
// CTA: 16 batch rows (bx), 32 timesteps (by). Warp w owns m-tiles 2w, 2w+1 (A-hi resident).
__global__ void __launch_bounds__(NT, 2) xz_wmma(
    const float* __restrict__ x, const float* __restrict__ b0)
{
    extern __shared__ char smc[];
    float* b0rep = reinterpret_cast<float*>(smc + X1_B0R);
    const int tid = threadIdx.x, wid = tid >> 5;
    const int row0 = blockIdx.x * ROWS, t0 = blockIdx.y * 32;

    // b0 replicated [m][16]
    for (int i = tid; i < 4096; i += NT) b0rep[i] = b0[i >> 4];

    // resident A-hi for 2 m-tiles x 4 k-tiles
    FragA ah[2][4];
#pragma unroll
    for (int i = 0; i < 2; ++i)
#pragma unroll
        for (int kt = 0; kt < 4; ++kt)
            wmma::load_matrix_sync(ah[i][kt], g_W0h + (wid*2+i)*16*72 + kt*16, 72);

    // x staging mapping: thread -> (row, kgroup)
    const int xrw = tid >> 4, kg = tid & 15;
    const float* xp = x + (size_t)(row0 + xrw)*(TSEQ*FIN) + kg*4;
    float4 xv = *reinterpret_cast<const float4*>(xp + (size_t)t0*64);
    __syncthreads();   // b0rep ready

    for (int tp = 0; tp < 32; ++tp) {
        const int t = t0 + tp, p = tp & 1;
        __nv_bfloat16* sh = reinterpret_cast<__nv_bfloat16*>(smc + X1_XS + p*4608);
        __nv_bfloat16* sl = sh + 1152;   // 2304 bytes
        // stage x(t) bf16 hi/lo: [row][k] ld 72
        {
            float vx[4] = {xv.x, xv.y, xv.z, xv.w};
            __nv_bfloat16 hi[4], lo[4];
#pragma unroll
            for (int j = 0; j < 4; ++j) {
                hi[j] = __float2bfloat16(vx[j]);
                lo[j] = __float2bfloat16(vx[j] - __bfloat162float(hi[j]));
            }
            *reinterpret_cast<__nv_bfloat162*>(sh + xrw*72 + kg*4)     = __nv_bfloat162(hi[0], hi[1]);
            *reinterpret_cast<__nv_bfloat162*>(sh + xrw*72 + kg*4 + 2) = __nv_bfloat162(hi[2], hi[3]);
            *reinterpret_cast<__nv_bfloat162*>(sl + xrw*72 + kg*4)     = __nv_bfloat162(lo[0], lo[1]);
            *reinterpret_cast<__nv_bfloat162*>(sl + xrw*72 + kg*4 + 2) = __nv_bfloat162(lo[2], lo[3]);
        }
        __syncthreads();

        // prefetch x(t+1)
        if (tp < 31) xv = *reinterpret_cast<const float4*>(xp + (size_t)(t+1)*64);

        FragC acc0, acc1;
        wmma::load_matrix_sync(acc0, b0rep + (wid*2  )*256, 16, wmma::mem_row_major);
        wmma::load_matrix_sync(acc1, b0rep + (wid*2+1)*256, 16, wmma::mem_row_major);
        FragB bh, bl;
        FragA al;
#pragma unroll
        for (int kt = 0; kt < 4; ++kt) {
            wmma::load_matrix_sync(bh, sh + kt*16, 72);
            wmma::load_matrix_sync(bl, sl + kt*16, 72);
            wmma::mma_sync(acc0, ah[0][kt], bh, acc0);
            wmma::mma_sync(acc0, ah[0][kt], bl, acc0);
            wmma::load_matrix_sync(al, g_W0l + (wid*2  )*16*72 + kt*16, 72);
            wmma::mma_sync(acc0, al, bh, acc0);
            wmma::mma_sync(acc1, ah[1][kt], bh, acc1);
            wmma::mma_sync(acc1, ah[1][kt], bl, acc1);
            wmma::load_matrix_sync(al, g_W0l + (wid*2+1)*16*72 + kt*16, 72);
            wmma::mma_sync(acc1, al, bh, acc1);
        }
        float* gp = g_xz + (size_t)(blockIdx.x*256 + t) * 4096;
        wmma::store_matrix_sync(gp + (wid*2  )*256, acc0, 16, wmma::mem_row_major);
        wmma::store_matrix_sync(gp + (wid*2+1)*256, acc1, 16, wmma::mem_row_major);
        // no second sync: stage[p] rewritten only at tp+2, after sync at tp+1
    }
}

// ========== PHASE 2: wmma recurrent loop (A hi+lo register-resident) ==========
__global__ void __launch_bounds__(NT, 1) lstm3_rec_wmma(
    const float* __restrict__ b1, const float* __restrict__ b2,
    const float* __restrict__ Wd, const float* __restrict__ bd,
    float* __restrict__ out)
{
    extern __shared__ char smc[];
    const int tid = threadIdx.x, wid = tid >> 5, bx = blockIdx.x;
    const int lw = wid - 4;

    for (int i = tid; i < 4352; i += NT) reinterpret_cast<uint32_t*>(smc + BTO)[i] = 0u;

    {
        const float* gp = g_xz + (size_t)bx*256*4096 + tid*4;
        uint32_t sa = smem_u32(smc + XZO) + tid*16;
#pragma unroll
        for (int i2 = 0; i2 < 4; ++i2) cpasync16(sa + i2*4096, gp + i2*1024);
        asm volatile("cp.async.commit_group;" ::: "memory");
    }

    // resident A hi AND lo fragments
    FragA ah[16], al[16];
    if (wid < 4) {
#pragma unroll
        for (int i = 0; i < 4; ++i)
#pragma unroll
            for (int kk = 0; kk < 4; ++kk) {
                wmma::load_matrix_sync(ah[i*4+kk], g_A0h + (wid*4+i)*16*72 + kk*16, 72);
                wmma::load_matrix_sync(al[i*4+kk], g_A0l + (wid*4+i)*16*72 + kk*16, 72);
            }
    } else {
#pragma unroll
        for (int t2 = 0; t2 < 2; ++t2) {
            const int mt = lw*2 + t2;
#pragma unroll
            for (int kk = 0; kk < 4; ++kk) {
                wmma::load_matrix_sync(ah[t2*6+kk], g_A1Wh + mt*16*72 + kk*16, 72);
                wmma::load_matrix_sync(al[t2*6+kk], g_A1Wl + mt*16*72 + kk*16, 72);
            }
#pragma unroll
            for (int u = 0; u < 2; ++u) {
                wmma::load_matrix_sync(ah[t2*6+4+u], g_A1Uh + mt*16*40 + u*16, 40);
                wmma::load_matrix_sync(al[t2*6+4+u], g_A1Ul + mt*16*40 + u*16, 40);
            }
        }
#pragma unroll
        for (int kk = 0; kk < 2; ++kk) {
            wmma::load_matrix_sync(ah[12+kk], g_A2Wh + lw*16*40 + kk*16, 40);
            wmma::load_matrix_sync(al[12+kk], g_A2Wl + lw*16*40 + kk*16, 40);
        }
        wmma::load_matrix_sync(ah[14], g_A2Uh + lw*16*24, 24);
        wmma::load_matrix_sync(al[14], g_A2Ul + lw*16*24, 24);
    }

    const int u0e = tid & 63,  q0 = tid >> 6;
    const int u1e = tid & 31,  q1 = (tid & 127) >> 5;
    const int u2e = tid & 15,  q2 = (tid & 63) >> 4;
    float b1r[4] = {0,0,0,0}, b2r[4] = {0,0,0,0};
    if (tid < 128) { b1r[0]=b1[u1e]; b1r[1]=b1[32+u1e]; b1r[2]=b1[64+u1e]; b1r[3]=b1[96+u1e]; }
    if (tid < 64)  { b2r[0]=b2[u2e]; b2r[1]=b2[16+u2e]; b2r[2]=b2[32+u2e]; b2r[3]=b2[48+u2e]; }
    float c0[4] = {0,0,0,0}, c1[4] = {0,0,0,0}, c2[4] = {0,0,0,0};

    float* z0 = reinterpret_cast<float*>(smc + Z0O);
    float* z1 = reinterpret_cast<float*>(smc + Z1O);
    float* z2 = reinterpret_cast<float*>(smc + Z2O);
    float* hf = reinterpret_cast<float*>(smc + HFO);

    asm volatile("cp.async.wait_group 0;" ::: "memory");
    __syncthreads();

    for (int s = 0; s < TSEQ + 2; ++s) {
        const int p = s & 1;

        if (s + 1 < TSEQ) {
            const float* gp = g_xz + (size_t)(bx*256 + s + 1)*4096 + tid*4;
            uint32_t sa = smem_u32(smc + XZO) + (p^1)*16384 + tid*16;
#pragma unroll
            for (int i2 = 0; i2 < 4; ++i2) cpasync16(sa + i2*4096, gp + i2*1024);
            asm volatile("cp.async.commit_group;" ::: "memory");
        }

        const __nv_bfloat16* br0h = reinterpret_cast<const __nv_bfloat16*>(smc + BTO + p*8704);
        const __nv_bfloat16* br0l = br0h + 1152;
        const __nv_bfloat16* br1h = br0h + 2304;
        const __nv_bfloat16* br1l = br0h + 2944;
        const __nv_bfloat16* br2h = br0h + 3584;
        const __nv_bfloat16* br2l = br0h + 3968;
        const float* xzp = reinterpret_cast<const float*>(smc + XZO + p*16384);

        FragB bh, bl;
        FragC acc[4];

        if (wid < 4) {
            if (s < TSEQ) {
#pragma unroll
                for (int i = 0; i < 4; ++i)
                    wmma::load_matrix_sync(acc[i], xzp + (wid*4+i)*256, 16, wmma::mem_row_major);
#pragma unroll
                for (int kk = 0; kk < 4; ++kk) {
                    wmma::load_matrix_sync(bh, br0h + kk*16, 72);
                    wmma::load_matrix_sync(bl, br0l + kk*16, 72);
#pragma unroll
                    for (int i = 0; i < 4; ++i) {
                        wmma::mma_sync(acc[i], ah[i*4+kk], bh, acc[i]);
                        wmma::mma_sync(acc[i], ah[i*4+kk], bl, acc[i]);
                        wmma::mma_sync(acc[i], al[i*4+kk], bh, acc[i]);
                    }
                }
#pragma unroll
                for (int i = 0; i < 4; ++i)
                    wmma::store_matrix_sync(z0 + (wid*4+i)*16*24, acc[i], 24, wmma::mem_row_major);
            }
        } else {
            if (s >= 1 && s <= TSEQ) {
                wmma::fill_fragment(acc[0], 0.0f);
                wmma::fill_fragment(acc[1], 0.0f);
#pragma unroll
                for (int kk = 0; kk < 4; ++kk) {
                    wmma::load_matrix_sync(bh, br0h + kk*16, 72);
                    wmma::load_matrix_sync(bl, br0l + kk*16, 72);
#pragma unroll
                    for (int t2 = 0; t2 < 2; ++t2) {
                        wmma::mma_sync(acc[t2], ah[t2*6+kk], bh, acc[t2]);
                        wmma::mma_sync(acc[t2], ah[t2*6+kk], bl, acc[t2]);
                        wmma::mma_sync(acc[t2], al[t2*6+kk], bh, acc[t2]);
                    }
                }
#pragma unroll
                for (int u = 0; u < 2; ++u) {
                    wmma::load_matrix_sync(bh, br1h + u*16, 40);
                    wmma::load_matrix_sync(bl, br1l + u*16, 40);
#pragma unroll
                    for (int t2 = 0; t2 < 2; ++t2) {
                        wmma::mma_sync(acc[t2], ah[t2*6+4+u], bh, acc[t2]);
                        wmma::mma_sync(acc[t2], ah[t2*6+4+u], bl, acc[t2]);
                        wmma::mma_sync(acc[t2], al[t2*6+4+u], bh, acc[t2]);
                    }
                }
#pragma unroll
                for (int t2 = 0; t2 < 2; ++t2)
                    wmma::store_matrix_sync(z1 + (lw*2+t2)*16*24, acc[t2], 24, wmma::mem_row_major);
            }
            if (s >= 2) {
                wmma::fill_fragment(acc[2], 0.0f);
#pragma unroll
                for (int kk = 0; kk < 2; ++kk) {
                    wmma::load_matrix_sync(bh, br1h + kk*16, 40);
                    wmma::load_matrix_sync(bl, br1l + kk*16, 40);
                    wmma::mma_sync(acc[2], ah[12+kk], bh, acc[2]);
                    wmma::mma_sync(acc[2], ah[12+kk], bl, acc[2]);
                    wmma::mma_sync(acc[2], al[12+kk], bh, acc[2]);
                }
                wmma::load_matrix_sync(bh, br2h, 24);
                wmma::load_matrix_sync(bl, br2l, 24);
                wmma::mma_sync(acc[2], ah[14], bh, acc[2]);
                wmma::mma_sync(acc[2], ah[14], bl, acc[2]);
                wmma::mma_sync(acc[2], al[14], bh, acc[2]);
                wmma::store_matrix_sync(z2 + lw*16*24, acc[2], 24, wmma::mem_row_major);
            }
        }
        __syncthreads();

        __nv_bfloat16* bw0h = reinterpret_cast<__nv_bfloat16*>(smc + BTO + (p^1)*8704);
        __nv_bfloat16* bw0l = bw0h + 1152;
        __nv_bfloat16* bw1h = bw0h + 2304;
        __nv_bfloat16* bw1l = bw0h + 2944;
        __nv_bfloat16* bw2h = bw0h + 3584;
        __nv_bfloat16* bw2l = bw0h + 3968;

        if (s < TSEQ) {
            float4 zi = *reinterpret_cast<const float4*>(z0 + (u0e      )*24 + 4*q0);
            float4 zf = *reinterpret_cast<const float4*>(z0 + (64 + u0e )*24 + 4*q0);
            float4 zg = *reinterpret_cast<const float4*>(z0 + (128 + u0e)*24 + 4*q0);
            float4 zo = *reinterpret_cast<const float4*>(z0 + (192 + u0e)*24 + 4*q0);
            float iv[4] = {zi.x,zi.y,zi.z,zi.w}, fv[4] = {zf.x,zf.y,zf.z,zf.w};
            float gv[4] = {zg.x,zg.y,zg.z,zg.w}, ov[4] = {zo.x,zo.y,zo.z,zo.w};
#pragma unroll
            for (int j = 0; j < 4; ++j) {
                float ig = sigap(iv[j]), fg = sigap(fv[j]);
                float gg = tanhap(gv[j]), og = sigap(ov[j]);
                c0[j] = fg * c0[j] + ig * gg;
                float h = og * tanhap(c0[j]);
                int n = 4*q0 + j;
                __nv_bfloat16 hi = __float2bfloat16(h);
                bw0h[n*72 + u0e] = hi;
                bw0l[n*72 + u0e] = __float2bfloat16(h - __bfloat162float(hi));
            }
        }
        if (s >= 1 && s <= TSEQ && tid < 128) {
            float4 zi = *reinterpret_cast<const float4*>(z1 + (u1e     )*24 + 4*q1);
            float4 zf = *reinterpret_cast<const float4*>(z1 + (32 + u1e)*24 + 4*q1);
            float4 zg = *reinterpret_cast<const float4*>(z1 + (64 + u1e)*24 + 4*q1);
            float4 zo = *reinterpret_cast<const float4*>(z1 + (96 + u1e)*24 + 4*q1);
            float iv[4] = {zi.x,zi.y,zi.z,zi.w}, fv[4] = {zf.x,zf.y,zf.z,zf.w};
            float gv[4] = {zg.x,zg.y,zg.z,zg.w}, ov[4] = {zo.x,zo.y,zo.z,zo.w};
#pragma unroll
            for (int j = 0; j < 4; ++j) {
                float ig = sigap(iv[j] + b1r[0]), fg = sigap(fv[j] + b1r[1]);
                float gg = tanhap(gv[j] + b1r[2]), og = sigap(ov[j] + b1r[3]);
                c1[j] = fg * c1[j] + ig * gg;
                float h = og * tanhap(c1[j]);
                int n = 4*q1 + j;
                __nv_bfloat16 hi = __float2bfloat16(h);
                bw1h[n*40 + u1e] = hi;
                bw1l[n*40 + u1e] = __float2bfloat16(h - __bfloat162float(hi));
            }
        }
        if (s >= 2 && tid < 64) {
            float4 zi = *reinterpret_cast<const float4*>(z2 + (u2e     )*24 + 4*q2);
            float4 zf = *reinterpret_cast<const float4*>(z2 + (16 + u2e)*24 + 4*q2);
            float4 zg = *reinterpret_cast<const float4*>(z2 + (32 + u2e)*24 + 4*q2);
            float4 zo = *reinterpret_cast<const float4*>(z2 + (48 + u2e)*24 + 4*q2);
            float iv[4] = {zi.x,zi.y,zi.z,zi.w}, fv[4] = {zf.x,zf.y,zf.z,zf.w};
            float gv[4] = {zg.x,zg.y,zg.z,zg.w}, ov[4] = {zo.x,zo.y,zo.z,zo.w};
#pragma unroll
            for (int j = 0; j < 4; ++j) {
                float ig = sigap(iv[j] + b2r[0]), fg = sigap(fv[j] + b2r[1]);
                float gg = tanhap(gv[j] + b2r[2]), og = sigap(ov[j] + b2r[3]);
                c2[j] = fg * c2[j] + ig * gg;
                float h = og * tanhap(c2[j]);
                int n = 4*q2 + j;
                __nv_bfloat16 hi = __float2bfloat16(h);
                bw2h[n*24 + u2e] = hi;
                bw2l[n*24 + u2e] = __float2bfloat16(h - __bfloat162float(hi));
                if (s == TSEQ + 1) hf[n*16 + u2e] = h;
            }
        }
        asm volatile("cp.async.wait_group 0;" ::: "memory");
        __syncthreads();
    }

    if (tid < 16) {
        float a = bd[0];
#pragma unroll
        for (int u = 0; u < 16; ++u) a += hf[tid*16 + u] * Wd[u];
        out[bx*ROWS + tid] = a;
    }
}

extern "C" void kernel_launch(void* const* d_in, const int* in_sizes, int n_in,
                              void* d_out, int out_size)
{
    (void)in_sizes; (void)n_in; (void)out_size;
    const float* x  = (const float*)d_in[0];
    const float* W0 = (const float*)d_in[1];
    const float* U0 = (const float*)d_in[2];
    const float* b0 = (const float*)d_in[3];
    const float* W1 = (const float*)d_in[4];
    const float* U1 = (const float*)d_in[5];
    const float* b1 = (const float*)d_in[6];
    const float* W2 = (const float*)d_in[7];
    const float* U2 = (const float*)d_in[8];
    const float* b2 = (const float*)d_in[9];
    const float* Wd = (const float*)d_in[10];
    const float* bd = (const float*)d_in[11];
    float* out = (float*)d_out;

    cudaFuncSetAttribute(xz_wmma, cudaFuncAttributeMaxDynamicSharedMemorySize, X1_BYTES);
    cudaFuncSetAttribute(lstm3_rec_wmma, cudaFuncAttributeMaxDynamicSharedMemorySize, SMEM2);

    wconv_kernel<<<32, 256>>>(W0, U0, W1, U1, W2, U2);
    xz_wmma<<<dim3(NBLK, 8), NT, X1_BYTES>>>(x, b0);
    lstm3_rec_wmma<<<NBLK, NT, SMEM2>>>(b1, b2, Wd, bd, out);
}